// round 1
// baseline (speedup 1.0000x reference)
#include <cuda_runtime.h>
#include <cstdint>
#include <cmath>

// Problem dims
// B=32, S=513 (T=512 ctx + 1 query), D=1024, K=256, V=256, H=2048, O=256
#define PB 32
#define PT 512
#define PD 1024
#define PK 256
#define PV 256
#define PH 2048
#define PO 256

// ---------------- device scratch (no allocations allowed) ----------------
__device__ float g_xK[(size_t)PB * PT * PK];            // 16 MB  [b][t][k]
__device__ float g_xV[(size_t)PB * PT * PV];            // 16 MB  [b][t][v]
__device__ float g_xQ[PB * PK];
__device__ float g_L0[(size_t)PB * PT * PH];            // 128 MB [b][t][h]
__device__ float g_G [(size_t)PB * PT * PT];            // 32 MB  [b][t][t']
__device__ int   g_last[PB * PH];                       // slot -> last win step (-1 = original)
__device__ float g_q0[PB * PH];                         // W_hi0[b,h]·xQ[b]
__device__ float g_qk[PB * PT];                         // xK[b,t]·xQ[b]
__device__ float g_wt[PB * PH];                         // softmax weight (0 for replaced slots)
__device__ float g_wv[PB * PT];                         // softmax weight mapped to winning step t

// ---------------- packed f32x2 helpers (sm_103a FFMA2) ----------------
__device__ __forceinline__ unsigned long long dup2(float x) {
    unsigned long long r;
    asm("mov.b64 %0, {%1,%1};" : "=l"(r) : "f"(x));
    return r;
}
__device__ __forceinline__ void fma2(unsigned long long& d, unsigned long long a, unsigned long long b) {
    asm("fma.rn.f32x2 %0, %1, %2, %0;" : "+l"(d) : "l"(a), "l"(b));
}

// ---------------- tiled fp32 GEMM: C[M,N] = A[M,K] @ B[N,K]^T ----------------
// 128x128 tile, BK=16, 256 threads, 8x8 per thread, FFMA2 inner loop.
// ASKIP: A row m maps to physical row m + m/512 (skips the 513th row of each batch in x).
template <bool ASKIP>
__global__ void __launch_bounds__(256) gemm128(
    const float* __restrict__ Ag, const float* __restrict__ Bg, float* __restrict__ Cg,
    int M, int N, int Kd, long sA, long sB, long sC)
{
    const float* A = Ag + (long)blockIdx.z * sA;
    const float* B = Bg + (long)blockIdx.z * sB;
    float*       C = Cg + (long)blockIdx.z * sC;
    const int m0 = blockIdx.y * 128;
    const int n0 = blockIdx.x * 128;

    __shared__ __align__(16) float As[16][128];
    __shared__ __align__(16) float Bs[16][128];

    const int tid = threadIdx.x;
    const int tx = tid & 15;        // 0..15 -> N
    const int ty = tid >> 4;        // 0..15 -> M
    const int lr = tid >> 2;        // 0..63 load row
    const int lc = (tid & 3) * 4;   // 0,4,8,12 load col

    alignas(16) unsigned long long acc[8][4];
    #pragma unroll
    for (int i = 0; i < 8; i++)
        #pragma unroll
        for (int j = 0; j < 4; j++) acc[i][j] = 0ull;

    for (int k0 = 0; k0 < Kd; k0 += 16) {
        #pragma unroll
        for (int h = 0; h < 2; h++) {
            int m = m0 + lr + h * 64;
            long arow = ASKIP ? (long)(m + (m >> 9)) : (long)m;
            float4 va = *reinterpret_cast<const float4*>(A + arow * (long)Kd + k0 + lc);
            As[lc + 0][lr + h * 64] = va.x;
            As[lc + 1][lr + h * 64] = va.y;
            As[lc + 2][lr + h * 64] = va.z;
            As[lc + 3][lr + h * 64] = va.w;
            int n = n0 + lr + h * 64;
            float4 vb = *reinterpret_cast<const float4*>(B + (long)n * Kd + k0 + lc);
            Bs[lc + 0][lr + h * 64] = vb.x;
            Bs[lc + 1][lr + h * 64] = vb.y;
            Bs[lc + 2][lr + h * 64] = vb.z;
            Bs[lc + 3][lr + h * 64] = vb.w;
        }
        __syncthreads();
        #pragma unroll
        for (int kk = 0; kk < 16; kk++) {
            float4 a0 = *reinterpret_cast<const float4*>(&As[kk][ty * 8]);
            float4 a1 = *reinterpret_cast<const float4*>(&As[kk][ty * 8 + 4]);
            const unsigned long long* bp =
                reinterpret_cast<const unsigned long long*>(&Bs[kk][tx * 8]);
            unsigned long long b2[4] = { bp[0], bp[1], bp[2], bp[3] };
            unsigned long long a2[8] = { dup2(a0.x), dup2(a0.y), dup2(a0.z), dup2(a0.w),
                                         dup2(a1.x), dup2(a1.y), dup2(a1.z), dup2(a1.w) };
            #pragma unroll
            for (int i = 0; i < 8; i++)
                #pragma unroll
                for (int j = 0; j < 4; j++)
                    fma2(acc[i][j], a2[i], b2[j]);
        }
        __syncthreads();
    }

    #pragma unroll
    for (int i = 0; i < 8; i++) {
        long m = m0 + ty * 8 + i;
        float* cr = C + m * (long)N + n0 + tx * 8;
        const float* af = reinterpret_cast<const float*>(acc[i]);
        *reinterpret_cast<float4*>(cr)     = make_float4(af[0], af[1], af[2], af[3]);
        *reinterpret_cast<float4*>(cr + 4) = make_float4(af[4], af[5], af[6], af[7]);
    }
}

// ---------------- xQ = x[b, 512, :] @ W_Q^T ; also written to d_out segment ----------------
__global__ void xq_kernel(const float* __restrict__ x, const float* __restrict__ WQ,
                          float* __restrict__ out_xq)
{
    int b = blockIdx.x;
    int w = threadIdx.x >> 5, lane = threadIdx.x & 31;
    int n = blockIdx.y * 8 + w;
    const float* xr = x + ((long)b * 513 + 512) * PD;
    const float* wr = WQ + (long)n * PD;
    float s = 0.f;
    for (int k = lane * 4; k < PD; k += 128) {
        float4 a = *reinterpret_cast<const float4*>(xr + k);
        float4 c = *reinterpret_cast<const float4*>(wr + k);
        s += a.x * c.x + a.y * c.y + a.z * c.z + a.w * c.w;
    }
    #pragma unroll
    for (int o = 16; o; o >>= 1) s += __shfl_down_sync(0xffffffffu, s, o);
    if (!lane) {
        g_xQ[b * PK + n] = s;
        out_xq[b * PK + n] = s;
    }
}

// ---------------- batched rowdot: out[b,r] = Rows[b,r,:]·xQ[b,:]  (Kd = 256) ----------------
__global__ void batched_dot(const float* __restrict__ Rows, long rStride,
                            float* __restrict__ outp, int oStride)
{
    int b = blockIdx.x;
    int w = threadIdx.x >> 5, lane = threadIdx.x & 31;
    int r = blockIdx.y * 8 + w;
    const float* row = Rows + (long)b * rStride + (long)r * PK;
    const float* v = g_xQ + b * PK;
    float s = 0.f;
    for (int k = lane * 4; k < PK; k += 128) {
        float4 a = *reinterpret_cast<const float4*>(row + k);
        float4 q = *reinterpret_cast<const float4*>(v + k);
        s += a.x * q.x + a.y * q.y + a.z * q.z + a.w * q.w;
    }
    #pragma unroll
    for (int o = 16; o; o >>= 1) s += __shfl_down_sync(0xffffffffu, s, o);
    if (!lane) outp[b * oStride + r] = s;
}

// ---------------- sequential one-winner scan (one block per batch) ----------------
// At step t: logit[h] = last[h]<0 ? L0[b,t,h] : G[b,t,last[h]]; winner = argmax (ties -> lowest h).
__global__ void __launch_bounds__(256) scan_kernel()
{
    const int b = blockIdx.x, tid = threadIdx.x;
    __shared__ int   last_s[PH];
    __shared__ float grow[2][PT];
    __shared__ float redv[8];
    __shared__ int   redi[8];

    const float* L0b = g_L0 + (size_t)b * PT * PH;
    const float* Gb  = g_G  + (size_t)b * PT * PT;

    #pragma unroll
    for (int i = 0; i < 8; i++) last_s[i * 256 + tid] = -1;

    float nxt[8];
    #pragma unroll
    for (int i = 0; i < 8; i++) nxt[i] = L0b[i * 256 + tid];
    grow[0][tid]       = Gb[tid];
    grow[0][256 + tid] = Gb[256 + tid];
    __syncthreads();

    const int lane = tid & 31, w = tid >> 5;

    for (int t = 0; t < PT; t++) {
        float cur[8];
        #pragma unroll
        for (int i = 0; i < 8; i++) cur[i] = nxt[i];

        // software prefetch of row t+1 (state-independent)
        if (t + 1 < PT) {
            const float* Lr = L0b + (size_t)(t + 1) * PH;
            #pragma unroll
            for (int i = 0; i < 8; i++) nxt[i] = Lr[i * 256 + tid];
            const float* Gr = Gb + (size_t)(t + 1) * PT;
            grow[(t + 1) & 1][tid]       = Gr[tid];
            grow[(t + 1) & 1][256 + tid] = Gr[256 + tid];
        }

        const float* gr = grow[t & 1];
        float bv = -3.4e38f;
        int bh = 0x7fffffff;
        #pragma unroll
        for (int i = 0; i < 8; i++) {
            int h = i * 256 + tid;
            int l = last_s[h];
            float v = (l < 0) ? cur[i] : gr[l];
            if (v > bv || (v == bv && h < bh)) { bv = v; bh = h; }
        }
        #pragma unroll
        for (int o = 16; o; o >>= 1) {
            float ov = __shfl_down_sync(0xffffffffu, bv, o);
            int   oh = __shfl_down_sync(0xffffffffu, bh, o);
            if (ov > bv || (ov == bv && oh < bh)) { bv = ov; bh = oh; }
        }
        if (!lane) { redv[w] = bv; redi[w] = bh; }
        __syncthreads();
        if (tid == 0) {
            float mv = redv[0]; int mh = redi[0];
            #pragma unroll
            for (int j = 1; j < 8; j++)
                if (redv[j] > mv || (redv[j] == mv && redi[j] < mh)) { mv = redv[j]; mh = redi[j]; }
            last_s[mh] = t;
        }
        __syncthreads();
    }

    #pragma unroll
    for (int i = 0; i < 8; i++) g_last[b * PH + i * 256 + tid] = last_s[i * 256 + tid];
}

// ---------------- softmax over final logits; split weights into wt (original) / wv (by step) ----------------
__global__ void softmax_kernel()
{
    int b = blockIdx.x, tid = threadIdx.x;
    __shared__ float red[8];

    g_wv[b * PT + tid]       = 0.f;
    g_wv[b * PT + 256 + tid] = 0.f;

    float l[8]; int ls[8];
    float mx = -3.4e38f;
    #pragma unroll
    for (int i = 0; i < 8; i++) {
        int h = i * 256 + tid;
        int t = g_last[b * PH + h];
        ls[i] = t;
        l[i] = (t < 0) ? g_q0[b * PH + h] : g_qk[b * PT + t];
        mx = fmaxf(mx, l[i]);
    }
    int lane = tid & 31, w = tid >> 5;
    #pragma unroll
    for (int o = 16; o; o >>= 1) mx = fmaxf(mx, __shfl_xor_sync(0xffffffffu, mx, o));
    if (!lane) red[w] = mx;
    __syncthreads();
    mx = red[0];
    #pragma unroll
    for (int j = 1; j < 8; j++) mx = fmaxf(mx, red[j]);

    float s = 0.f;
    #pragma unroll
    for (int i = 0; i < 8; i++) { l[i] = expf(l[i] - mx); s += l[i]; }
    #pragma unroll
    for (int o = 16; o; o >>= 1) s += __shfl_xor_sync(0xffffffffu, s, o);
    __syncthreads();
    if (!lane) red[w] = s;
    __syncthreads();
    s = 0.f;
    #pragma unroll
    for (int j = 0; j < 8; j++) s += red[j];

    float inv = 1.f / s;
    #pragma unroll
    for (int i = 0; i < 8; i++) {
        int h = i * 256 + tid;
        float wgt = l[i] * inv;
        if (ls[i] < 0) {
            g_wt[b * PH + h] = wgt;
        } else {
            g_wt[b * PH + h] = 0.f;
            g_wv[b * PT + ls[i]] = wgt;   // injective: each t owned by at most one slot
        }
    }
}

// ---------------- mhn_out = W_oh0@wt + xV^T@wv, then out = mhn_out @ W_proj^T ----------------
__global__ void __launch_bounds__(256) mhn_proj_kernel(
    const float* __restrict__ W_oh0, const float* __restrict__ W_proj, float* __restrict__ outp)
{
    int b = blockIdx.x, tid = threadIdx.x, lane = tid & 31, w = tid >> 5;
    __shared__ float wt_s[PH];
    __shared__ float wv_s[PT];
    __shared__ float mhn_s[PV];

    #pragma unroll
    for (int i = 0; i < 8; i++) wt_s[i * 256 + tid] = g_wt[b * PH + i * 256 + tid];
    wv_s[tid]       = g_wv[b * PT + tid];
    wv_s[256 + tid] = g_wv[b * PT + 256 + tid];
    __syncthreads();

    // xV term: thread per v (coalesced over v)
    float acc = 0.f;
    const float* xvb = g_xV + (size_t)b * PT * PV;
    #pragma unroll 4
    for (int t = 0; t < PT; t++) acc += wv_s[t] * xvb[(size_t)t * PV + tid];
    mhn_s[tid] = acc;
    __syncthreads();

    // W_oh0 term: warp per v
    for (int pass = 0; pass < 32; pass++) {
        int v = pass * 8 + w;
        const float* row = W_oh0 + ((long)b * PV + v) * PH;
        float s = 0.f;
        #pragma unroll 4
        for (int h = lane * 4; h < PH; h += 128) {
            float4 a = *reinterpret_cast<const float4*>(row + h);
            s += a.x * wt_s[h] + a.y * wt_s[h + 1] + a.z * wt_s[h + 2] + a.w * wt_s[h + 3];
        }
        #pragma unroll
        for (int o = 16; o; o >>= 1) s += __shfl_down_sync(0xffffffffu, s, o);
        if (!lane) mhn_s[v] += s;
    }
    __syncthreads();

    // projection: warp per o
    for (int pass = 0; pass < 32; pass++) {
        int o = pass * 8 + w;
        const float* pr = W_proj + (long)o * PV;
        float s = 0.f;
        for (int vv = lane * 4; vv < PV; vv += 128) {
            float4 a = *reinterpret_cast<const float4*>(pr + vv);
            s += a.x * mhn_s[vv] + a.y * mhn_s[vv + 1] + a.z * mhn_s[vv + 2] + a.w * mhn_s[vv + 3];
        }
        #pragma unroll
        for (int oo = 16; oo; oo >>= 1) s += __shfl_down_sync(0xffffffffu, s, oo);
        if (!lane) outp[b * PO + o] = s;
    }
}

// ---------------- reinst[b,d] = sum_h wt[h]*W_reinst0[b,h,d] + sum_t wv[t]*x[b,t,d] ----------------
__global__ void __launch_bounds__(256) reinst_kernel(
    const float* __restrict__ W_reinst0, const float* __restrict__ x, float* __restrict__ outp)
{
    int b = blockIdx.x, tid = threadIdx.x;
    int d0 = blockIdx.y * 256;
    __shared__ float wt_s[PH];
    __shared__ float wv_s[PT];
    #pragma unroll
    for (int i = 0; i < 8; i++) wt_s[i * 256 + tid] = g_wt[b * PH + i * 256 + tid];
    wv_s[tid]       = g_wv[b * PT + tid];
    wv_s[256 + tid] = g_wv[b * PT + 256 + tid];
    __syncthreads();

    float acc = 0.f;
    const float* Wb = W_reinst0 + (size_t)b * PH * PD + d0 + tid;
    #pragma unroll 8
    for (int h = 0; h < PH; h++) acc += wt_s[h] * Wb[(size_t)h * PD];
    const float* xb = x + (size_t)b * 513 * PD + d0 + tid;
    #pragma unroll 8
    for (int t = 0; t < PT; t++) acc += wv_s[t] * xb[(size_t)t * PD];

    outp[b * PD + d0 + tid] = acc;
}

// ---------------- launch ----------------
extern "C" void kernel_launch(void* const* d_in, const int* in_sizes, int n_in,
                              void* d_out, int out_size)
{
    const float* x         = (const float*)d_in[0];
    const float* W_Q       = (const float*)d_in[1];
    const float* W_K       = (const float*)d_in[2];
    const float* W_V       = (const float*)d_in[3];
    const float* W_proj    = (const float*)d_in[4];
    const float* W_hi0     = (const float*)d_in[5];
    const float* W_oh0     = (const float*)d_in[6];
    const float* W_reinst0 = (const float*)d_in[7];
    float* out = (float*)d_out;

    float *pxK, *pxV, *pL0, *pG, *pq0, *pqk;
    cudaGetSymbolAddress((void**)&pxK, g_xK);
    cudaGetSymbolAddress((void**)&pxV, g_xV);
    cudaGetSymbolAddress((void**)&pL0, g_L0);
    cudaGetSymbolAddress((void**)&pG,  g_G);
    cudaGetSymbolAddress((void**)&pq0, g_q0);
    cudaGetSymbolAddress((void**)&pqk, g_qk);

    // output layout: [out 32x256 | reinst 32x1024 | xQ 32x256]
    float* out_main   = out;
    float* out_reinst = out + PB * PO;               // 8192
    float* out_xq     = out + PB * PO + PB * PD;     // 40960

    // 1) xK = ctx @ W_K^T, xV = ctx @ W_V^T   (M=16384, N=256, K=1024; ASKIP maps past the query rows)
    gemm128<true><<<dim3(2, 128, 1), 256>>>(x, W_K, pxK, PB * PT, PK, PD, 0, 0, 0);
    gemm128<true><<<dim3(2, 128, 1), 256>>>(x, W_V, pxV, PB * PT, PV, PD, 0, 0, 0);

    // 2) xQ (also writes the third output segment)
    xq_kernel<<<dim3(PB, PK / 8), 256>>>(x, W_Q, out_xq);

    // 3) L0[b,t,h] = xK[b,t]·W_hi0[b,h]   (per-batch M=512, N=2048, K=256)
    gemm128<false><<<dim3(16, 4, PB), 256>>>(pxK, W_hi0, pL0, PT, PH, PK,
                                             (long)PT * PK, (long)PH * PK, (long)PT * PH);

    // 4) G[b,t,t'] = xK[b,t]·xK[b,t']     (per-batch M=N=512, K=256)
    gemm128<false><<<dim3(4, 4, PB), 256>>>(pxK, pxK, pG, PT, PT, PK,
                                            (long)PT * PK, (long)PT * PK, (long)PT * PT);

    // 5) sequential winner scan
    scan_kernel<<<PB, 256>>>();

    // 6) final logit pieces
    batched_dot<<<dim3(PB, PH / 8), 256>>>(W_hi0, (long)PH * PK, pq0, PH);
    batched_dot<<<dim3(PB, PT / 8), 256>>>(pxK, (long)PT * PK, pqk, PT);

    // 7) softmax + weight split
    softmax_kernel<<<PB, 256>>>();

    // 8) outputs
    mhn_proj_kernel<<<PB, 256>>>(W_oh0, W_proj, out_main);
    reinst_kernel<<<dim3(PB, PD / 256), 256>>>(W_reinst0, x, out_reinst);
}

// round 2
// speedup vs baseline: 1.0850x; 1.0850x over previous
#include <cuda_runtime.h>
#include <cstdint>
#include <cmath>

// Problem dims: B=32, S=513 (T=512 ctx + 1 query), D=1024, K=256, V=256, H=2048, O=256
#define PB 32
#define PT 512
#define PD 1024
#define PK 256
#define PV 256
#define PH 2048
#define PO 256

// ---------------- device scratch ----------------
__device__ float g_xK[(size_t)PB * PT * PK];            // 16 MB  [b][t][k]
__device__ float g_xQ[PB * PK];
__device__ float g_L0[(size_t)PB * PT * PH];            // 128 MB [b][t][h]
__device__ float g_G [(size_t)PB * PT * PT];            // 32 MB  [b][t][t']
__device__ int   g_last[PB * PH];
__device__ float g_q0[PB * PH];
__device__ float g_qk[PB * PT];
__device__ float g_wt[PB * PH];
__device__ float g_wv[PB * PT];
__device__ float g_ybar[PB * PD];                       // sum_t wv[t]*x[b,t,:]

__device__ __forceinline__ void fma2(unsigned long long& d, unsigned long long a, unsigned long long b) {
    asm("fma.rn.f32x2 %0, %1, %2, %0;" : "+l"(d) : "l"(a), "l"(b));
}

// ---------------- tiled fp32 GEMM: C[M,N] = A[M,K] @ B[N,K]^T ----------------
// 128x128 tile, BK=16, 256 threads, 8x8 per thread.
// Double-buffered smem; A stored DUPLICATED (each value twice) so FFMA2 a-operands
// come straight out of LDS.128 as packed pairs — no per-kk dup movs.
#define AS_STRIDE 260              // padded (16B aligned rows, conflict-free k-shift)
#define BS_STRIDE 132
#define A_BUF (16 * AS_STRIDE)     // floats per A buffer (dup: 256 cols)
#define B_BUF (16 * BS_STRIDE)
#define B_OFF (2 * A_BUF)
#define GEMM_SMEM ((2 * A_BUF + 2 * B_BUF) * 4)   // 50176 bytes

template <bool ASKIP>
__global__ void __launch_bounds__(256) gemm128(
    const float* __restrict__ Ag, const float* __restrict__ Bg, float* __restrict__ Cg,
    int M, int N, int Kd, long sA, long sB, long sC)
{
    extern __shared__ float sm[];
    const float* A = Ag + (long)blockIdx.z * sA;
    const float* B = Bg + (long)blockIdx.z * sB;
    float*       C = Cg + (long)blockIdx.z * sC;
    const int m0 = blockIdx.y * 128;
    const int n0 = blockIdx.x * 128;

    const int tid = threadIdx.x;
    const int tx = tid & 15;
    const int ty = tid >> 4;
    const int lr = tid >> 2;
    const int lc = (tid & 3) * 4;

    unsigned long long acc[8][4];
    #pragma unroll
    for (int i = 0; i < 8; i++)
        #pragma unroll
        for (int j = 0; j < 4; j++) acc[i][j] = 0ull;

    float4 va[2], vb[2];

    // initial load of k-block 0
    #pragma unroll
    for (int h = 0; h < 2; h++) {
        int m = m0 + lr + h * 64;
        long arow = ASKIP ? (long)(m + (m >> 9)) : (long)m;
        va[h] = *reinterpret_cast<const float4*>(A + arow * (long)Kd + lc);
        int n = n0 + lr + h * 64;
        vb[h] = *reinterpret_cast<const float4*>(B + (long)n * Kd + lc);
    }
    #pragma unroll
    for (int h = 0; h < 2; h++) {
        int m = lr + h * 64;
        float* ab = sm + 2 * m;
        *reinterpret_cast<float2*>(ab + (lc + 0) * AS_STRIDE) = make_float2(va[h].x, va[h].x);
        *reinterpret_cast<float2*>(ab + (lc + 1) * AS_STRIDE) = make_float2(va[h].y, va[h].y);
        *reinterpret_cast<float2*>(ab + (lc + 2) * AS_STRIDE) = make_float2(va[h].z, va[h].z);
        *reinterpret_cast<float2*>(ab + (lc + 3) * AS_STRIDE) = make_float2(va[h].w, va[h].w);
        float* bb = sm + B_OFF + m;
        bb[(lc + 0) * BS_STRIDE] = vb[h].x;
        bb[(lc + 1) * BS_STRIDE] = vb[h].y;
        bb[(lc + 2) * BS_STRIDE] = vb[h].z;
        bb[(lc + 3) * BS_STRIDE] = vb[h].w;
    }
    __syncthreads();

    const int nk = Kd >> 4;
    int buf = 0;
    for (int kb = 0; kb < nk; kb++) {
        // prefetch next k-block into registers
        if (kb + 1 < nk) {
            int k0 = (kb + 1) * 16;
            #pragma unroll
            for (int h = 0; h < 2; h++) {
                int m = m0 + lr + h * 64;
                long arow = ASKIP ? (long)(m + (m >> 9)) : (long)m;
                va[h] = *reinterpret_cast<const float4*>(A + arow * (long)Kd + k0 + lc);
                int n = n0 + lr + h * 64;
                vb[h] = *reinterpret_cast<const float4*>(B + (long)n * Kd + k0 + lc);
            }
        }
        // compute current buffer
        {
            const float* ap = sm + buf * A_BUF + ty * 16;
            const float* bp = sm + B_OFF + buf * B_BUF + tx * 8;
            #pragma unroll
            for (int kk = 0; kk < 16; kk++) {
                ulonglong2 A0 = *reinterpret_cast<const ulonglong2*>(ap);
                ulonglong2 A1 = *reinterpret_cast<const ulonglong2*>(ap + 4);
                ulonglong2 A2 = *reinterpret_cast<const ulonglong2*>(ap + 8);
                ulonglong2 A3 = *reinterpret_cast<const ulonglong2*>(ap + 12);
                ulonglong2 B0 = *reinterpret_cast<const ulonglong2*>(bp);
                ulonglong2 B1 = *reinterpret_cast<const ulonglong2*>(bp + 4);
                unsigned long long av[8] = {A0.x, A0.y, A1.x, A1.y, A2.x, A2.y, A3.x, A3.y};
                unsigned long long bv[4] = {B0.x, B0.y, B1.x, B1.y};
                #pragma unroll
                for (int i = 0; i < 8; i++)
                    #pragma unroll
                    for (int j = 0; j < 4; j++)
                        fma2(acc[i][j], av[i], bv[j]);
                ap += AS_STRIDE;
                bp += BS_STRIDE;
            }
        }
        // store prefetched regs into the other buffer
        if (kb + 1 < nk) {
            int obuf = buf ^ 1;
            #pragma unroll
            for (int h = 0; h < 2; h++) {
                int m = lr + h * 64;
                float* ab = sm + obuf * A_BUF + 2 * m;
                *reinterpret_cast<float2*>(ab + (lc + 0) * AS_STRIDE) = make_float2(va[h].x, va[h].x);
                *reinterpret_cast<float2*>(ab + (lc + 1) * AS_STRIDE) = make_float2(va[h].y, va[h].y);
                *reinterpret_cast<float2*>(ab + (lc + 2) * AS_STRIDE) = make_float2(va[h].z, va[h].z);
                *reinterpret_cast<float2*>(ab + (lc + 3) * AS_STRIDE) = make_float2(va[h].w, va[h].w);
                float* bb = sm + B_OFF + obuf * B_BUF + m;
                bb[(lc + 0) * BS_STRIDE] = vb[h].x;
                bb[(lc + 1) * BS_STRIDE] = vb[h].y;
                bb[(lc + 2) * BS_STRIDE] = vb[h].z;
                bb[(lc + 3) * BS_STRIDE] = vb[h].w;
            }
        }
        __syncthreads();
        buf ^= 1;
    }

    #pragma unroll
    for (int i = 0; i < 8; i++) {
        long m = m0 + ty * 8 + i;
        float* cr = C + m * (long)N + n0 + tx * 8;
        float2 f0 = *reinterpret_cast<float2*>(&acc[i][0]);
        float2 f1 = *reinterpret_cast<float2*>(&acc[i][1]);
        float2 f2 = *reinterpret_cast<float2*>(&acc[i][2]);
        float2 f3 = *reinterpret_cast<float2*>(&acc[i][3]);
        *reinterpret_cast<float4*>(cr)     = make_float4(f0.x, f0.y, f1.x, f1.y);
        *reinterpret_cast<float4*>(cr + 4) = make_float4(f2.x, f2.y, f3.x, f3.y);
    }
}

// ---------------- xQ = x[b, 512, :] @ W_Q^T ----------------
__global__ void xq_kernel(const float* __restrict__ x, const float* __restrict__ WQ,
                          float* __restrict__ out_xq)
{
    int b = blockIdx.x;
    int w = threadIdx.x >> 5, lane = threadIdx.x & 31;
    int n = blockIdx.y * 8 + w;
    const float* xr = x + ((long)b * 513 + 512) * PD;
    const float* wr = WQ + (long)n * PD;
    float s = 0.f;
    for (int k = lane * 4; k < PD; k += 128) {
        float4 a = *reinterpret_cast<const float4*>(xr + k);
        float4 c = *reinterpret_cast<const float4*>(wr + k);
        s += a.x * c.x + a.y * c.y + a.z * c.z + a.w * c.w;
    }
    #pragma unroll
    for (int o = 16; o; o >>= 1) s += __shfl_down_sync(0xffffffffu, s, o);
    if (!lane) {
        g_xQ[b * PK + n] = s;
        out_xq[b * PK + n] = s;
    }
}

// ---------------- batched rowdot: out[b,r] = Rows[b,r,:]·xQ[b,:] (Kd=256) ----------------
__global__ void batched_dot(const float* __restrict__ Rows, long rStride,
                            float* __restrict__ outp, int oStride)
{
    int b = blockIdx.x;
    int w = threadIdx.x >> 5, lane = threadIdx.x & 31;
    int r = blockIdx.y * 8 + w;
    const float* row = Rows + (long)b * rStride + (long)r * PK;
    const float* v = g_xQ + b * PK;
    float s = 0.f;
    for (int k = lane * 4; k < PK; k += 128) {
        float4 a = *reinterpret_cast<const float4*>(row + k);
        float4 q = *reinterpret_cast<const float4*>(v + k);
        s += a.x * q.x + a.y * q.y + a.z * q.z + a.w * q.w;
    }
    #pragma unroll
    for (int o = 16; o; o >>= 1) s += __shfl_down_sync(0xffffffffu, s, o);
    if (!lane) outp[b * oStride + r] = s;
}

// ---------------- sequential one-winner scan (one block per batch) ----------------
// last[] in registers (thread owns h = i*256+tid); redux.sync warp argmax;
// block winner computed redundantly; ONE __syncthreads per step.
__global__ void __launch_bounds__(256) scan_kernel()
{
    const int b = blockIdx.x, tid = threadIdx.x;
    __shared__ float grow[3][PT];
    __shared__ unsigned redm[2][8];
    __shared__ unsigned redh[2][8];

    const float* L0b = g_L0 + (size_t)b * PT * PH;
    const float* Gb  = g_G  + (size_t)b * PT * PT;

    int last[8];
    #pragma unroll
    for (int i = 0; i < 8; i++) last[i] = -1;

    float cur[8], n1[8];
    #pragma unroll
    for (int i = 0; i < 8; i++) cur[i] = L0b[i * 256 + tid];
    #pragma unroll
    for (int i = 0; i < 8; i++) n1[i] = L0b[PH + i * 256 + tid];
    grow[0][tid]       = Gb[tid];
    grow[0][256 + tid] = Gb[256 + tid];
    grow[1][tid]       = Gb[PT + tid];
    grow[1][256 + tid] = Gb[PT + 256 + tid];
    __syncthreads();

    const int lane = tid & 31, w = tid >> 5;
    int sc = 0, sw = 2;

    for (int t = 0; t < PT; t++) {
        float n2[8];
        if (t + 2 < PT) {
            const float* Lr = L0b + (size_t)(t + 2) * PH;
            #pragma unroll
            for (int i = 0; i < 8; i++) n2[i] = Lr[i * 256 + tid];
            const float* Gr = Gb + (size_t)(t + 2) * PT;
            float ga = Gr[tid], gb = Gr[256 + tid];
            grow[sw][tid]       = ga;
            grow[sw][256 + tid] = gb;
        }

        const float* gr = grow[sc];
        unsigned bestm;
        int besth;
        {
            float v = last[0] < 0 ? cur[0] : gr[last[0]];
            unsigned u = __float_as_uint(v);
            bestm = (u & 0x80000000u) ? ~u : (u | 0x80000000u);
            besth = tid;
        }
        #pragma unroll
        for (int i = 1; i < 8; i++) {
            float v = last[i] < 0 ? cur[i] : gr[last[i]];
            unsigned u = __float_as_uint(v);
            u = (u & 0x80000000u) ? ~u : (u | 0x80000000u);
            if (u > bestm) { bestm = u; besth = i * 256 + tid; }  // ascending h: strict > keeps lowest
        }
        unsigned m1 = __reduce_max_sync(0xffffffffu, bestm);
        unsigned hc = (bestm == m1) ? (unsigned)besth : 0xffffffffu;
        unsigned mh = __reduce_min_sync(0xffffffffu, hc);
        if (lane == 0) { redm[t & 1][w] = m1; redh[t & 1][w] = mh; }
        __syncthreads();

        unsigned bm = redm[t & 1][0], bh = redh[t & 1][0];
        #pragma unroll
        for (int j = 1; j < 8; j++) {
            unsigned m2 = redm[t & 1][j], h2 = redh[t & 1][j];
            if (m2 > bm || (m2 == bm && h2 < bh)) { bm = m2; bh = h2; }
        }
        if ((int)(bh & 255u) == tid) last[bh >> 8] = t;

        #pragma unroll
        for (int i = 0; i < 8; i++) { cur[i] = n1[i]; n1[i] = n2[i]; }
        sc = (sc == 2) ? 0 : sc + 1;
        sw = (sw == 2) ? 0 : sw + 1;
    }

    #pragma unroll
    for (int i = 0; i < 8; i++) g_last[b * PH + i * 256 + tid] = last[i];
}

// ---------------- softmax over final logits; split weights wt / wv ----------------
__global__ void softmax_kernel()
{
    int b = blockIdx.x, tid = threadIdx.x;
    __shared__ float red[8];

    g_wv[b * PT + tid]       = 0.f;
    g_wv[b * PT + 256 + tid] = 0.f;

    float l[8]; int ls[8];
    float mx = -3.4e38f;
    #pragma unroll
    for (int i = 0; i < 8; i++) {
        int h = i * 256 + tid;
        int t = g_last[b * PH + h];
        ls[i] = t;
        l[i] = (t < 0) ? g_q0[b * PH + h] : g_qk[b * PT + t];
        mx = fmaxf(mx, l[i]);
    }
    int lane = tid & 31, w = tid >> 5;
    #pragma unroll
    for (int o = 16; o; o >>= 1) mx = fmaxf(mx, __shfl_xor_sync(0xffffffffu, mx, o));
    if (!lane) red[w] = mx;
    __syncthreads();
    mx = red[0];
    #pragma unroll
    for (int j = 1; j < 8; j++) mx = fmaxf(mx, red[j]);

    float s = 0.f;
    #pragma unroll
    for (int i = 0; i < 8; i++) { l[i] = expf(l[i] - mx); s += l[i]; }
    #pragma unroll
    for (int o = 16; o; o >>= 1) s += __shfl_xor_sync(0xffffffffu, s, o);
    __syncthreads();
    if (!lane) red[w] = s;
    __syncthreads();
    s = 0.f;
    #pragma unroll
    for (int j = 0; j < 8; j++) s += red[j];

    float inv = 1.f / s;
    #pragma unroll
    for (int i = 0; i < 8; i++) {
        int h = i * 256 + tid;
        float wgt = l[i] * inv;
        if (ls[i] < 0) {
            g_wt[b * PH + h] = wgt;
        } else {
            g_wt[b * PH + h] = 0.f;
            g_wv[b * PT + ls[i]] = wgt;
        }
    }
}

// ---------------- reinst[b,d] = sum_h wt[h]*W_reinst0[b,h,d] + ybar[b,d]; also writes ybar ----------------
__global__ void __launch_bounds__(256) reinst_kernel(
    const float* __restrict__ W_reinst0, const float* __restrict__ x, float* __restrict__ outp)
{
    int b = blockIdx.x, tid = threadIdx.x;
    int d0 = blockIdx.y * 256;
    __shared__ float wt_s[PH];
    __shared__ float wv_s[PT];
    #pragma unroll
    for (int i = 0; i < 8; i++) wt_s[i * 256 + tid] = g_wt[b * PH + i * 256 + tid];
    wv_s[tid]       = g_wv[b * PT + tid];
    wv_s[256 + tid] = g_wv[b * PT + 256 + tid];
    __syncthreads();

    float yb = 0.f;
    const float* xb = x + (size_t)b * 513 * PD + d0 + tid;
    #pragma unroll 8
    for (int t = 0; t < PT; t++) yb += wv_s[t] * xb[(size_t)t * PD];

    float acc = yb;
    const float* Wb = W_reinst0 + (size_t)b * PH * PD + d0 + tid;
    #pragma unroll 8
    for (int h = 0; h < PH; h++) acc += wt_s[h] * Wb[(size_t)h * PD];

    g_ybar[b * PD + d0 + tid] = yb;
    outp[b * PD + d0 + tid] = acc;
}

// ---------------- mhn = W_oh0@wt + ybar@W_V^T; out = mhn @ W_proj^T ----------------
__global__ void __launch_bounds__(256) mhn_proj_kernel(
    const float* __restrict__ W_oh0, const float* __restrict__ W_V,
    const float* __restrict__ W_proj, float* __restrict__ outp)
{
    int b = blockIdx.x, tid = threadIdx.x, lane = tid & 31, w = tid >> 5;
    __shared__ float wt_s[PH];
    __shared__ float yb_s[PD];
    __shared__ float mhn_s[PV];

    #pragma unroll
    for (int i = 0; i < 8; i++) wt_s[i * 256 + tid] = g_wt[b * PH + i * 256 + tid];
    #pragma unroll
    for (int i = 0; i < 4; i++) yb_s[i * 256 + tid] = g_ybar[b * PD + i * 256 + tid];
    __syncthreads();

    for (int pass = 0; pass < 32; pass++) {
        int v = pass * 8 + w;
        const float* row = W_oh0 + ((long)b * PV + v) * PH;
        float s = 0.f;
        #pragma unroll 4
        for (int h = lane * 4; h < PH; h += 128) {
            float4 a = *reinterpret_cast<const float4*>(row + h);
            s += a.x * wt_s[h] + a.y * wt_s[h + 1] + a.z * wt_s[h + 2] + a.w * wt_s[h + 3];
        }
        const float* wvr = W_V + (long)v * PD;
        #pragma unroll 4
        for (int d = lane * 4; d < PD; d += 128) {
            float4 a = *reinterpret_cast<const float4*>(wvr + d);
            s += a.x * yb_s[d] + a.y * yb_s[d + 1] + a.z * yb_s[d + 2] + a.w * yb_s[d + 3];
        }
        #pragma unroll
        for (int o = 16; o; o >>= 1) s += __shfl_down_sync(0xffffffffu, s, o);
        if (!lane) mhn_s[v] = s;
    }
    __syncthreads();

    for (int pass = 0; pass < 32; pass++) {
        int o = pass * 8 + w;
        const float* pr = W_proj + (long)o * PV;
        float s = 0.f;
        for (int vv = lane * 4; vv < PV; vv += 128) {
            float4 a = *reinterpret_cast<const float4*>(pr + vv);
            s += a.x * mhn_s[vv] + a.y * mhn_s[vv + 1] + a.z * mhn_s[vv + 2] + a.w * mhn_s[vv + 3];
        }
        #pragma unroll
        for (int oo = 16; oo; oo >>= 1) s += __shfl_down_sync(0xffffffffu, s, oo);
        if (!lane) outp[b * PO + o] = s;
    }
}

// ---------------- launch ----------------
extern "C" void kernel_launch(void* const* d_in, const int* in_sizes, int n_in,
                              void* d_out, int out_size)
{
    const float* x         = (const float*)d_in[0];
    const float* W_Q       = (const float*)d_in[1];
    const float* W_K       = (const float*)d_in[2];
    const float* W_V       = (const float*)d_in[3];
    const float* W_proj    = (const float*)d_in[4];
    const float* W_hi0     = (const float*)d_in[5];
    const float* W_oh0     = (const float*)d_in[6];
    const float* W_reinst0 = (const float*)d_in[7];
    float* out = (float*)d_out;

    float *pxK, *pL0, *pG, *pq0, *pqk;
    cudaGetSymbolAddress((void**)&pxK, g_xK);
    cudaGetSymbolAddress((void**)&pL0, g_L0);
    cudaGetSymbolAddress((void**)&pG,  g_G);
    cudaGetSymbolAddress((void**)&pq0, g_q0);
    cudaGetSymbolAddress((void**)&pqk, g_qk);

    cudaFuncSetAttribute((const void*)gemm128<true>,
                         cudaFuncAttributeMaxDynamicSharedMemorySize, GEMM_SMEM);
    cudaFuncSetAttribute((const void*)gemm128<false>,
                         cudaFuncAttributeMaxDynamicSharedMemorySize, GEMM_SMEM);

    // output layout: [out 32x256 | reinst 32x1024 | xQ 32x256]
    float* out_main   = out;
    float* out_reinst = out + PB * PO;
    float* out_xq     = out + PB * PO + PB * PD;

    // 1) xK = ctx @ W_K^T  (M=16384, N=256, K=1024)
    gemm128<true><<<dim3(2, 128, 1), 256, GEMM_SMEM>>>(x, W_K, pxK, PB * PT, PK, PD, 0, 0, 0);

    // 2) xQ
    xq_kernel<<<dim3(PB, PK / 8), 256>>>(x, W_Q, out_xq);

    // 3) L0[b,t,h] = xK[b,t]·W_hi0[b,h]
    gemm128<false><<<dim3(16, 4, PB), 256, GEMM_SMEM>>>(pxK, W_hi0, pL0, PT, PH, PK,
                                                        (long)PT * PK, (long)PH * PK, (long)PT * PH);

    // 4) G[b,t,t'] = xK[b,t]·xK[b,t']
    gemm128<false><<<dim3(4, 4, PB), 256, GEMM_SMEM>>>(pxK, pxK, pG, PT, PT, PK,
                                                       (long)PT * PK, (long)PT * PK, (long)PT * PT);

    // 5) sequential winner scan
    scan_kernel<<<PB, 256>>>();

    // 6) final logit pieces
    batched_dot<<<dim3(PB, PH / 8), 256>>>(W_hi0, (long)PH * PK, pq0, PH);
    batched_dot<<<dim3(PB, PT / 8), 256>>>(pxK, (long)PT * PK, pqk, PT);

    // 7) softmax + weight split
    softmax_kernel<<<PB, 256>>>();

    // 8) reinst (also produces ybar), then mhn + projection (uses ybar@W_V^T — no xV GEMM)
    reinst_kernel<<<dim3(PB, PD / 256), 256>>>(W_reinst0, x, out_reinst);
    mhn_proj_kernel<<<PB, 256>>>(W_oh0, W_V, W_proj, out_main);
}

// round 4
// speedup vs baseline: 1.1188x; 1.0311x over previous
#include <cuda_runtime.h>
#include <cstdint>
#include <cmath>

// Problem dims: B=32, S=513 (T=512 ctx + 1 query), D=1024, K=256, V=256, H=2048, O=256
#define PB 32
#define PT 512
#define PD 1024
#define PK 256
#define PV 256
#define PH 2048
#define PO 256

// ---------------- device scratch ----------------
__device__ float g_xK[(size_t)PB * PT * PK];            // 16 MB
__device__ float g_xQ[PB * PK];
__device__ float g_L0[(size_t)PB * PT * PH];            // 128 MB
__device__ float g_G [(size_t)PB * PT * PT];            // 32 MB
__device__ int   g_last[PB * PH];
__device__ float g_q0[PB * PH];
__device__ float g_qk[PB * PT];
__device__ float g_wt[PB * PH];
__device__ float g_wv[PB * PT];
__device__ float g_ybar[PB * PD];
__device__ float g_mhn[PB * PV];

__device__ __forceinline__ void fma2(unsigned long long& d, unsigned long long a, unsigned long long b) {
    asm("fma.rn.f32x2 %0, %1, %2, %0;" : "+l"(d) : "l"(a), "l"(b));
}

// ---------------- tiled fp32 GEMM: C[M,N] = A[M,K] @ B[N,K]^T ----------------
// 128x128 tile, BK=16, 256 threads, 8x8 per thread, FFMA2 inner loop (dup-A smem).
// Double smem buffer (1 bar/iter). __launch_bounds__(256,2) -> <=128 regs -> 2 CTAs/SM.
// Conflict-free: A dup-store via lr=tid&63 map; B frag read as two 16B chunks (tx*4, 64+tx*4).
#define AS_STRIDE 264
#define BS_STRIDE 132
#define A_BUF (16 * AS_STRIDE)
#define B_BUF (16 * BS_STRIDE)
#define B_OFF (2 * A_BUF)
#define GEMM_SMEM ((2 * A_BUF + 2 * B_BUF) * 4)   // 50688 bytes

template <bool ASKIP>
__global__ void __launch_bounds__(256, 2) gemm128(
    const float* __restrict__ Ag, const float* __restrict__ Bg, float* __restrict__ Cg,
    int M, int N, int Kd, long sA, long sB, long sC)
{
    extern __shared__ float sm[];
    const float* A = Ag + (long)blockIdx.z * sA;
    const float* B = Bg + (long)blockIdx.z * sB;
    float*       C = Cg + (long)blockIdx.z * sC;
    const int m0 = blockIdx.y * 128;
    const int n0 = blockIdx.x * 128;

    const int tid = threadIdx.x;
    const int tx = tid & 15;
    const int ty = tid >> 4;
    const int lr = tid & 63;           // row within half-tile (loader)
    const int lc = (tid >> 6) * 4;     // k-chunk 0,4,8,12 (loader)

    unsigned long long acc[8][4];
    #pragma unroll
    for (int i = 0; i < 8; i++)
        #pragma unroll
        for (int j = 0; j < 4; j++) acc[i][j] = 0ull;

    float4 va[2], vb[2];

    // load k-block 0
    #pragma unroll
    for (int h = 0; h < 2; h++) {
        int m = m0 + lr + h * 64;
        long arow = ASKIP ? (long)(m + (m >> 9)) : (long)m;
        va[h] = *reinterpret_cast<const float4*>(A + arow * (long)Kd + lc);
        int n = n0 + lr + h * 64;
        vb[h] = *reinterpret_cast<const float4*>(B + (long)n * Kd + lc);
    }
    #pragma unroll
    for (int h = 0; h < 2; h++) {
        int r = lr + h * 64;
        float* ab = sm + 2 * r;
        *reinterpret_cast<float2*>(ab + (lc + 0) * AS_STRIDE) = make_float2(va[h].x, va[h].x);
        *reinterpret_cast<float2*>(ab + (lc + 1) * AS_STRIDE) = make_float2(va[h].y, va[h].y);
        *reinterpret_cast<float2*>(ab + (lc + 2) * AS_STRIDE) = make_float2(va[h].z, va[h].z);
        *reinterpret_cast<float2*>(ab + (lc + 3) * AS_STRIDE) = make_float2(va[h].w, va[h].w);
        float* bb = sm + B_OFF + r;
        bb[(lc + 0) * BS_STRIDE] = vb[h].x;
        bb[(lc + 1) * BS_STRIDE] = vb[h].y;
        bb[(lc + 2) * BS_STRIDE] = vb[h].z;
        bb[(lc + 3) * BS_STRIDE] = vb[h].w;
    }
    __syncthreads();

    const int nk = Kd >> 4;
    int buf = 0;
    for (int kb = 0; kb < nk; kb++) {
        if (kb + 1 < nk) {
            int k0 = (kb + 1) * 16;
            #pragma unroll
            for (int h = 0; h < 2; h++) {
                int m = m0 + lr + h * 64;
                long arow = ASKIP ? (long)(m + (m >> 9)) : (long)m;
                va[h] = *reinterpret_cast<const float4*>(A + arow * (long)Kd + k0 + lc);
                int n = n0 + lr + h * 64;
                vb[h] = *reinterpret_cast<const float4*>(B + (long)n * Kd + k0 + lc);
            }
        }
        {
            const float* ap = sm + buf * A_BUF + ty * 16;
            const float* bp = sm + B_OFF + buf * B_BUF + tx * 4;
            #pragma unroll
            for (int kk = 0; kk < 16; kk++) {
                ulonglong2 A0 = *reinterpret_cast<const ulonglong2*>(ap);
                ulonglong2 A1 = *reinterpret_cast<const ulonglong2*>(ap + 4);
                ulonglong2 A2 = *reinterpret_cast<const ulonglong2*>(ap + 8);
                ulonglong2 A3 = *reinterpret_cast<const ulonglong2*>(ap + 12);
                ulonglong2 B0 = *reinterpret_cast<const ulonglong2*>(bp);
                ulonglong2 B1 = *reinterpret_cast<const ulonglong2*>(bp + 64);
                unsigned long long av[8] = {A0.x, A0.y, A1.x, A1.y, A2.x, A2.y, A3.x, A3.y};
                #pragma unroll
                for (int i = 0; i < 8; i++) {
                    fma2(acc[i][0], av[i], B0.x);
                    fma2(acc[i][1], av[i], B0.y);
                    fma2(acc[i][2], av[i], B1.x);
                    fma2(acc[i][3], av[i], B1.y);
                }
                ap += AS_STRIDE;
                bp += BS_STRIDE;
            }
        }
        if (kb + 1 < nk) {
            int obuf = buf ^ 1;
            #pragma unroll
            for (int h = 0; h < 2; h++) {
                int r = lr + h * 64;
                float* ab = sm + obuf * A_BUF + 2 * r;
                *reinterpret_cast<float2*>(ab + (lc + 0) * AS_STRIDE) = make_float2(va[h].x, va[h].x);
                *reinterpret_cast<float2*>(ab + (lc + 1) * AS_STRIDE) = make_float2(va[h].y, va[h].y);
                *reinterpret_cast<float2*>(ab + (lc + 2) * AS_STRIDE) = make_float2(va[h].z, va[h].z);
                *reinterpret_cast<float2*>(ab + (lc + 3) * AS_STRIDE) = make_float2(va[h].w, va[h].w);
                float* bb = sm + B_OFF + obuf * B_BUF + r;
                bb[(lc + 0) * BS_STRIDE] = vb[h].x;
                bb[(lc + 1) * BS_STRIDE] = vb[h].y;
                bb[(lc + 2) * BS_STRIDE] = vb[h].z;
                bb[(lc + 3) * BS_STRIDE] = vb[h].w;
            }
        }
        __syncthreads();
        buf ^= 1;
    }

    #pragma unroll
    for (int i = 0; i < 8; i++) {
        long m = m0 + ty * 8 + i;
        float* cr = C + m * (long)N + n0;
        float2 f0 = *reinterpret_cast<float2*>(&acc[i][0]);
        float2 f1 = *reinterpret_cast<float2*>(&acc[i][1]);
        float2 f2 = *reinterpret_cast<float2*>(&acc[i][2]);
        float2 f3 = *reinterpret_cast<float2*>(&acc[i][3]);
        *reinterpret_cast<float4*>(cr + tx * 4)      = make_float4(f0.x, f0.y, f1.x, f1.y);
        *reinterpret_cast<float4*>(cr + 64 + tx * 4) = make_float4(f2.x, f2.y, f3.x, f3.y);
    }
}

// ---------------- xQ = x[b, 512, :] @ W_Q^T ----------------
__global__ void xq_kernel(const float* __restrict__ x, const float* __restrict__ WQ,
                          float* __restrict__ out_xq)
{
    int b = blockIdx.x;
    int w = threadIdx.x >> 5, lane = threadIdx.x & 31;
    int n = blockIdx.y * 8 + w;
    const float* xr = x + ((long)b * 513 + 512) * PD;
    const float* wr = WQ + (long)n * PD;
    float s = 0.f;
    for (int k = lane * 4; k < PD; k += 128) {
        float4 a = *reinterpret_cast<const float4*>(xr + k);
        float4 c = *reinterpret_cast<const float4*>(wr + k);
        s += a.x * c.x + a.y * c.y + a.z * c.z + a.w * c.w;
    }
    #pragma unroll
    for (int o = 16; o; o >>= 1) s += __shfl_down_sync(0xffffffffu, s, o);
    if (!lane) {
        g_xQ[b * PK + n] = s;
        out_xq[b * PK + n] = s;
    }
}

// ---------------- batched rowdot: out[b,r] = Rows[b,r,:]·xQ[b,:] (Kd=256) ----------------
__global__ void batched_dot(const float* __restrict__ Rows, long rStride,
                            float* __restrict__ outp, int oStride)
{
    int b = blockIdx.x;
    int w = threadIdx.x >> 5, lane = threadIdx.x & 31;
    int r = blockIdx.y * 8 + w;
    const float* row = Rows + (long)b * rStride + (long)r * PK;
    const float* v = g_xQ + b * PK;
    float s = 0.f;
    for (int k = lane * 4; k < PK; k += 128) {
        float4 a = *reinterpret_cast<const float4*>(row + k);
        float4 q = *reinterpret_cast<const float4*>(v + k);
        s += a.x * q.x + a.y * q.y + a.z * q.z + a.w * q.w;
    }
    #pragma unroll
    for (int o = 16; o; o >>= 1) s += __shfl_down_sync(0xffffffffu, s, o);
    if (!lane) outp[b * oStride + r] = s;
}

// ---------------- sequential one-winner scan (one block per batch) ----------------
__global__ void __launch_bounds__(256) scan_kernel()
{
    const int b = blockIdx.x, tid = threadIdx.x;
    __shared__ float grow[3][PT];
    __shared__ unsigned redm[2][8];
    __shared__ unsigned redh[2][8];

    const float* L0b = g_L0 + (size_t)b * PT * PH;
    const float* Gb  = g_G  + (size_t)b * PT * PT;

    int last[8];
    #pragma unroll
    for (int i = 0; i < 8; i++) last[i] = -1;

    float cur[8], n1[8];
    #pragma unroll
    for (int i = 0; i < 8; i++) cur[i] = L0b[i * 256 + tid];
    #pragma unroll
    for (int i = 0; i < 8; i++) n1[i] = L0b[PH + i * 256 + tid];
    grow[0][tid]       = Gb[tid];
    grow[0][256 + tid] = Gb[256 + tid];
    grow[1][tid]       = Gb[PT + tid];
    grow[1][256 + tid] = Gb[PT + 256 + tid];
    __syncthreads();

    const int lane = tid & 31, w = tid >> 5;
    int sc = 0, sw = 2;

    for (int t = 0; t < PT; t++) {
        float n2[8];
        if (t + 2 < PT) {
            const float* Lr = L0b + (size_t)(t + 2) * PH;
            #pragma unroll
            for (int i = 0; i < 8; i++) n2[i] = Lr[i * 256 + tid];
            const float* Gr = Gb + (size_t)(t + 2) * PT;
            float ga = Gr[tid], gb = Gr[256 + tid];
            grow[sw][tid]       = ga;
            grow[sw][256 + tid] = gb;
        }

        const float* gr = grow[sc];
        unsigned bestm;
        int besth;
        {
            float v = last[0] < 0 ? cur[0] : gr[last[0]];
            unsigned u = __float_as_uint(v);
            bestm = (u & 0x80000000u) ? ~u : (u | 0x80000000u);
            besth = tid;
        }
        #pragma unroll
        for (int i = 1; i < 8; i++) {
            float v = last[i] < 0 ? cur[i] : gr[last[i]];
            unsigned u = __float_as_uint(v);
            u = (u & 0x80000000u) ? ~u : (u | 0x80000000u);
            if (u > bestm) { bestm = u; besth = i * 256 + tid; }
        }
        unsigned m1 = __reduce_max_sync(0xffffffffu, bestm);
        unsigned hc = (bestm == m1) ? (unsigned)besth : 0xffffffffu;
        unsigned mh = __reduce_min_sync(0xffffffffu, hc);
        if (lane == 0) { redm[t & 1][w] = m1; redh[t & 1][w] = mh; }
        __syncthreads();

        unsigned bm = redm[t & 1][0], bh = redh[t & 1][0];
        #pragma unroll
        for (int j = 1; j < 8; j++) {
            unsigned m2 = redm[t & 1][j], h2 = redh[t & 1][j];
            if (m2 > bm || (m2 == bm && h2 < bh)) { bm = m2; bh = h2; }
        }
        if ((int)(bh & 255u) == tid) last[bh >> 8] = t;

        #pragma unroll
        for (int i = 0; i < 8; i++) { cur[i] = n1[i]; n1[i] = n2[i]; }
        sc = (sc == 2) ? 0 : sc + 1;
        sw = (sw == 2) ? 0 : sw + 1;
    }

    #pragma unroll
    for (int i = 0; i < 8; i++) g_last[b * PH + i * 256 + tid] = last[i];
}

// ---------------- softmax over final logits; split weights wt / wv ----------------
__global__ void softmax_kernel()
{
    int b = blockIdx.x, tid = threadIdx.x;
    __shared__ float red[8];

    g_wv[b * PT + tid]       = 0.f;
    g_wv[b * PT + 256 + tid] = 0.f;

    float l[8]; int ls[8];
    float mx = -3.4e38f;
    #pragma unroll
    for (int i = 0; i < 8; i++) {
        int h = i * 256 + tid;
        int t = g_last[b * PH + h];
        ls[i] = t;
        l[i] = (t < 0) ? g_q0[b * PH + h] : g_qk[b * PT + t];
        mx = fmaxf(mx, l[i]);
    }
    int lane = tid & 31, w = tid >> 5;
    #pragma unroll
    for (int o = 16; o; o >>= 1) mx = fmaxf(mx, __shfl_xor_sync(0xffffffffu, mx, o));
    if (!lane) red[w] = mx;
    __syncthreads();
    mx = red[0];
    #pragma unroll
    for (int j = 1; j < 8; j++) mx = fmaxf(mx, red[j]);

    float s = 0.f;
    #pragma unroll
    for (int i = 0; i < 8; i++) { l[i] = expf(l[i] - mx); s += l[i]; }
    #pragma unroll
    for (int o = 16; o; o >>= 1) s += __shfl_xor_sync(0xffffffffu, s, o);
    __syncthreads();
    if (!lane) red[w] = s;
    __syncthreads();
    s = 0.f;
    #pragma unroll
    for (int j = 0; j < 8; j++) s += red[j];

    float inv = 1.f / s;
    #pragma unroll
    for (int i = 0; i < 8; i++) {
        int h = i * 256 + tid;
        float wgt = l[i] * inv;
        if (ls[i] < 0) {
            g_wt[b * PH + h] = wgt;
        } else {
            g_wt[b * PH + h] = 0.f;
            g_wv[b * PT + ls[i]] = wgt;
        }
    }
}

// ---------------- reinst[b,d] = sum_h wt[h]*W_reinst0[b,h,d] + ybar[b,d]; writes ybar ----------------
__global__ void __launch_bounds__(256) reinst_kernel(
    const float* __restrict__ W_reinst0, const float* __restrict__ x, float* __restrict__ outp)
{
    int b = blockIdx.x, tid = threadIdx.x;
    int d0 = blockIdx.y * 256;
    __shared__ float wt_s[PH];
    __shared__ float wv_s[PT];
    #pragma unroll
    for (int i = 0; i < 8; i++) wt_s[i * 256 + tid] = g_wt[b * PH + i * 256 + tid];
    wv_s[tid]       = g_wv[b * PT + tid];
    wv_s[256 + tid] = g_wv[b * PT + 256 + tid];
    __syncthreads();

    float yb = 0.f;
    const float* xb = x + (size_t)b * 513 * PD + d0 + tid;
    #pragma unroll 8
    for (int t = 0; t < PT; t++) yb += wv_s[t] * xb[(size_t)t * PD];

    float acc = yb;
    const float* Wb = W_reinst0 + (size_t)b * PH * PD + d0 + tid;
    #pragma unroll 8
    for (int h = 0; h < PH; h++) acc += wt_s[h] * Wb[(size_t)h * PD];

    g_ybar[b * PD + d0 + tid] = yb;
    outp[b * PD + d0 + tid] = acc;
}

// ---------------- mhn[b,v] = W_oh0[b,v,:]@wt + W_V[v,:]@ybar  (grid: B x 8) ----------------
__global__ void __launch_bounds__(256) mhn_kernel(
    const float* __restrict__ W_oh0, const float* __restrict__ W_V)
{
    int b = blockIdx.x, tid = threadIdx.x, lane = tid & 31, w = tid >> 5;
    int v0 = blockIdx.y * 32;
    __shared__ float wt_s[PH];
    __shared__ float yb_s[PD];

    #pragma unroll
    for (int i = 0; i < 8; i++) wt_s[i * 256 + tid] = g_wt[b * PH + i * 256 + tid];
    #pragma unroll
    for (int i = 0; i < 4; i++) yb_s[i * 256 + tid] = g_ybar[b * PD + i * 256 + tid];
    __syncthreads();

    for (int pass = 0; pass < 4; pass++) {
        int v = v0 + pass * 8 + w;
        const float* row = W_oh0 + ((long)b * PV + v) * PH;
        float s = 0.f;
        #pragma unroll 4
        for (int h = lane * 4; h < PH; h += 128) {
            float4 a = *reinterpret_cast<const float4*>(row + h);
            s += a.x * wt_s[h] + a.y * wt_s[h + 1] + a.z * wt_s[h + 2] + a.w * wt_s[h + 3];
        }
        const float* wvr = W_V + (long)v * PD;
        #pragma unroll 4
        for (int d = lane * 4; d < PD; d += 128) {
            float4 a = *reinterpret_cast<const float4*>(wvr + d);
            s += a.x * yb_s[d] + a.y * yb_s[d + 1] + a.z * yb_s[d + 2] + a.w * yb_s[d + 3];
        }
        #pragma unroll
        for (int o = 16; o; o >>= 1) s += __shfl_down_sync(0xffffffffu, s, o);
        if (!lane) g_mhn[b * PV + v] = s;
    }
}

// ---------------- out[b,o] = mhn[b,:]@W_proj[o,:]  (grid: B x 8) ----------------
__global__ void __launch_bounds__(256) proj_kernel(
    const float* __restrict__ W_proj, float* __restrict__ outp)
{
    int b = blockIdx.x, tid = threadIdx.x, lane = tid & 31, w = tid >> 5;
    int o0 = blockIdx.y * 32;
    __shared__ float mhn_s[PV];
    if (tid < PV) mhn_s[tid] = g_mhn[b * PV + tid];
    __syncthreads();

    for (int pass = 0; pass < 4; pass++) {
        int o = o0 + pass * 8 + w;
        const float* pr = W_proj + (long)o * PV;
        float s = 0.f;
        for (int vv = lane * 4; vv < PV; vv += 128) {
            float4 a = *reinterpret_cast<const float4*>(pr + vv);
            s += a.x * mhn_s[vv] + a.y * mhn_s[vv + 1] + a.z * mhn_s[vv + 2] + a.w * mhn_s[vv + 3];
        }
        #pragma unroll
        for (int oo = 16; oo; oo >>= 1) s += __shfl_down_sync(0xffffffffu, s, oo);
        if (!lane) outp[b * PO + o] = s;
    }
}

// ---------------- launch ----------------
extern "C" void kernel_launch(void* const* d_in, const int* in_sizes, int n_in,
                              void* d_out, int out_size)
{
    const float* x         = (const float*)d_in[0];
    const float* W_Q       = (const float*)d_in[1];
    const float* W_K       = (const float*)d_in[2];
    const float* W_V       = (const float*)d_in[3];
    const float* W_proj    = (const float*)d_in[4];
    const float* W_hi0     = (const float*)d_in[5];
    const float* W_oh0     = (const float*)d_in[6];
    const float* W_reinst0 = (const float*)d_in[7];
    float* out = (float*)d_out;

    float *pxK, *pL0, *pG, *pq0, *pqk;
    cudaGetSymbolAddress((void**)&pxK, g_xK);
    cudaGetSymbolAddress((void**)&pL0, g_L0);
    cudaGetSymbolAddress((void**)&pG,  g_G);
    cudaGetSymbolAddress((void**)&pq0, g_q0);
    cudaGetSymbolAddress((void**)&pqk, g_qk);

    cudaFuncSetAttribute((const void*)gemm128<true>,
                         cudaFuncAttributeMaxDynamicSharedMemorySize, GEMM_SMEM);
    cudaFuncSetAttribute((const void*)gemm128<false>,
                         cudaFuncAttributeMaxDynamicSharedMemorySize, GEMM_SMEM);

    // output layout: [out 32x256 | reinst 32x1024 | xQ 32x256]
    float* out_main   = out;
    float* out_reinst = out + PB * PO;
    float* out_xq     = out + PB * PO + PB * PD;

    // 1) xK = ctx @ W_K^T  (M=16384, N=256, K=1024)
    gemm128<true><<<dim3(2, 128, 1), 256, GEMM_SMEM>>>(x, W_K, pxK, PB * PT, PK, PD, 0, 0, 0);

    // 2) xQ
    xq_kernel<<<dim3(PB, PK / 8), 256>>>(x, W_Q, out_xq);

    // 3) L0[b,t,h] = xK[b,t]·W_hi0[b,h]
    gemm128<false><<<dim3(16, 4, PB), 256, GEMM_SMEM>>>(pxK, W_hi0, pL0, PT, PH, PK,
                                                        (long)PT * PK, (long)PH * PK, (long)PT * PH);

    // 4) G[b,t,t'] = xK[b,t]·xK[b,t']
    gemm128<false><<<dim3(4, 4, PB), 256, GEMM_SMEM>>>(pxK, pxK, pG, PT, PT, PK,
                                                       (long)PT * PK, (long)PT * PK, (long)PT * PT);

    // 5) final logit pieces (independent of scan; issue first to keep order flexible)
    batched_dot<<<dim3(PB, PH / 8), 256>>>(W_hi0, (long)PH * PK, pq0, PH);
    batched_dot<<<dim3(PB, PT / 8), 256>>>(pxK, (long)PT * PK, pqk, PT);

    // 6) sequential winner scan
    scan_kernel<<<PB, 256>>>();

    // 7) softmax + weight split
    softmax_kernel<<<PB, 256>>>();

    // 8) outputs
    reinst_kernel<<<dim3(PB, PD / 256), 256>>>(W_reinst0, x, out_reinst);
    mhn_kernel<<<dim3(PB, 8), 256>>>(W_oh0, W_V);
    proj_kernel<<<dim3(PB, 8), 256>>>(W_proj, out_main);
}

// round 7
// speedup vs baseline: 1.4339x; 1.2817x over previous
#include <cuda_runtime.h>
#include <cstdint>
#include <cmath>

// Problem dims: B=32, S=513 (T=512 ctx + 1 query), D=1024, K=256, V=256, H=2048, O=256
#define PB 32
#define PT 512
#define PD 1024
#define PK 256
#define PV 256
#define PH 2048
#define PO 256

// ---------------- device scratch ----------------
__device__ float g_xK[(size_t)PB * PT * PK];            // 16 MB
__device__ float g_xQ[PB * PK];
__device__ float g_L0[(size_t)PB * PT * PH];            // 128 MB
__device__ float g_G [(size_t)PB * PT * PT];            // 32 MB
__device__ int   g_last[PB * PH];
__device__ float g_q0[PB * PH];
__device__ float g_qk[PB * PT];
__device__ float g_wt[PB * PH];
__device__ float g_wv[PB * PT];
__device__ float g_ybar[PB * PD];
__device__ float g_mhn[PB * PV];

// ================= mma.sync tf32 helpers (NOT arch-variant-gated) =================
__device__ __forceinline__ uint32_t smem_u32(const void* p) {
    uint32_t a;
    asm("{ .reg .u64 t; cvta.to.shared.u64 t, %1; cvt.u32.u64 %0, t; }" : "=r"(a) : "l"(p));
    return a;
}
__device__ __forceinline__ uint32_t tf32_hi(uint32_t raw) {
    uint32_t u;
    asm("cvt.rna.tf32.f32 %0, %1;" : "=r"(u) : "f"(__uint_as_float(raw)));
    return u;
}
__device__ __forceinline__ uint32_t tf32_lo(uint32_t raw, uint32_t hi) {
    float d = __uint_as_float(raw) - __uint_as_float(hi);
    uint32_t u;
    asm("cvt.rna.tf32.f32 %0, %1;" : "=r"(u) : "f"(d));
    return u;
}
__device__ __forceinline__ void ldmx4(uint32_t* r, uint32_t addr) {
    asm volatile("ldmatrix.sync.aligned.m8n8.x4.shared.b16 {%0,%1,%2,%3}, [%4];"
                 : "=r"(r[0]), "=r"(r[1]), "=r"(r[2]), "=r"(r[3]) : "r"(addr));
}
__device__ __forceinline__ void ldmx2(uint32_t* r, uint32_t addr) {
    asm volatile("ldmatrix.sync.aligned.m8n8.x2.shared.b16 {%0,%1}, [%2];"
                 : "=r"(r[0]), "=r"(r[1]) : "r"(addr));
}
__device__ __forceinline__ void mma8(float* c, const uint32_t* a, const uint32_t* b) {
    asm volatile(
        "mma.sync.aligned.m16n8k8.row.col.f32.tf32.tf32.f32 "
        "{%0,%1,%2,%3}, {%4,%5,%6,%7}, {%8,%9}, {%0,%1,%2,%3};"
        : "+f"(c[0]), "+f"(c[1]), "+f"(c[2]), "+f"(c[3])
        : "r"(a[0]), "r"(a[1]), "r"(a[2]), "r"(a[3]), "r"(b[0]), "r"(b[1]));
}
__device__ __forceinline__ void cp16(uint32_t dst, const void* src) {
    asm volatile("cp.async.ca.shared.global [%0], [%1], 16;" :: "r"(dst), "l"(src) : "memory");
}
__device__ __forceinline__ void cp_commit() {
    asm volatile("cp.async.commit_group;" ::: "memory");
}
__device__ __forceinline__ void cp_wait1() {
    asm volatile("cp.async.wait_group 1;" ::: "memory");
}
__device__ __forceinline__ void cp_wait0() {
    asm volatile("cp.async.wait_group 0;" ::: "memory");
}

// ================= TF32 3-split tensor-core GEMM =================
// C[M,N] = A[M,K] @ B[N,K]^T, fp32 in/out via hi*hi + hi*lo + lo*hi TF32 split.
// 128x128 CTA tile, BK=16, 256 threads (8 warps, 2x4 warp grid, 64x32 warp tile).
// cp.async double-buffered raw-fp32 smem (row pad 20 floats -> conflict-free ldmatrix);
// hi/lo conversion in registers after ldmatrix.
#define TSTRIDE 20                     // floats per smem row (16 data + 4 pad)
#define TILE_F (128 * TSTRIDE)         // floats per tile buffer

template <bool ASKIP>
__global__ void __launch_bounds__(256) gemm_mma(
    const float* __restrict__ Ag, const float* __restrict__ Bg, float* __restrict__ Cg,
    int N, int Kd, long sA, long sB, long sC)
{
    __shared__ __align__(16) float smA[2][TILE_F];
    __shared__ __align__(16) float smB[2][TILE_F];

    const float* A = Ag + (long)blockIdx.z * sA;
    const float* B = Bg + (long)blockIdx.z * sB;
    float*       C = Cg + (long)blockIdx.z * sC;
    const int m0 = blockIdx.y * 128;
    const int n0 = blockIdx.x * 128;
    const int tid = threadIdx.x, wid = tid >> 5, lane = tid & 31;
    const int wm = (wid & 1) * 64;         // warp M offset in tile
    const int wn = (wid >> 1) * 32;        // warp N offset in tile

    float acc[4][4][4];
    #pragma unroll
    for (int i = 0; i < 4; i++)
        #pragma unroll
        for (int j = 0; j < 4; j++)
            #pragma unroll
            for (int k = 0; k < 4; k++) acc[i][j][k] = 0.f;

    // producer: 512 16B transfers per matrix per chunk; thread does idx = tid, tid+256
    const int p_row0 = tid >> 2, p_q0 = tid & 3;          // idx = tid
    const int p_row1 = (tid + 256) >> 2, p_q1 = tid & 3;  // idx = tid+256

    const uint32_t sa0 = smem_u32(smA[0]);
    const uint32_t sb0 = smem_u32(smB[0]);

    // ldmatrix per-lane addressing
    const int a_r = (lane & 7) + ((lane >> 3) & 1) * 8;   // row within 16-row frag
    const int a_c = (lane >> 4) * 4;                      // col offset 0 or 4
    const int b_r = (lane & 7);
    const int b_c = ((lane >> 3) & 1) * 4;

    const uint32_t aOff = (uint32_t)(((wm + a_r) * TSTRIDE + a_c) * 4);
    const uint32_t bOff = (uint32_t)(((wn + b_r) * TSTRIDE + b_c) * 4);

    const int nc = Kd >> 4;

    // issue chunk c into buffer bu
    auto issue = [&](int c, int bu) {
        const int k0 = c * 16;
        {
            long am = (long)(m0 + p_row0);
            long ar = ASKIP ? (am + (am >> 9)) : am;
            cp16(sa0 + (uint32_t)((bu * TILE_F + p_row0 * TSTRIDE + p_q0 * 4) * 4),
                 A + ar * (long)Kd + k0 + p_q0 * 4);
            cp16(sb0 + (uint32_t)((bu * TILE_F + p_row0 * TSTRIDE + p_q0 * 4) * 4),
                 B + (long)(n0 + p_row0) * Kd + k0 + p_q0 * 4);
        }
        {
            long am = (long)(m0 + p_row1);
            long ar = ASKIP ? (am + (am >> 9)) : am;
            cp16(sa0 + (uint32_t)((bu * TILE_F + p_row1 * TSTRIDE + p_q1 * 4) * 4),
                 A + ar * (long)Kd + k0 + p_q1 * 4);
            cp16(sb0 + (uint32_t)((bu * TILE_F + p_row1 * TSTRIDE + p_q1 * 4) * 4),
                 B + (long)(n0 + p_row1) * Kd + k0 + p_q1 * 4);
        }
        cp_commit();
    };

    issue(0, 0);

    for (int c = 0; c < nc; c++) {
        const int bu = c & 1;
        if (c + 1 < nc) { issue(c + 1, bu ^ 1); cp_wait1(); }
        else            { cp_wait0(); }
        __syncthreads();

        const uint32_t aB = sa0 + (uint32_t)(bu * TILE_F * 4) + aOff;
        const uint32_t bB = sb0 + (uint32_t)(bu * TILE_F * 4) + bOff;

        #pragma unroll
        for (int k8 = 0; k8 < 2; k8++) {
            uint32_t ar[4][4], br[4][2];
            #pragma unroll
            for (int mi = 0; mi < 4; mi++)
                ldmx4(ar[mi], aB + (uint32_t)((mi * 16 * TSTRIDE) * 4 + k8 * 32));
            #pragma unroll
            for (int ni = 0; ni < 4; ni++)
                ldmx2(br[ni], bB + (uint32_t)((ni * 8 * TSTRIDE) * 4 + k8 * 32));

            uint32_t ah[4][4], bh[4][2];
            #pragma unroll
            for (int mi = 0; mi < 4; mi++)
                #pragma unroll
                for (int j = 0; j < 4; j++) ah[mi][j] = tf32_hi(ar[mi][j]);
            #pragma unroll
            for (int ni = 0; ni < 4; ni++)
                #pragma unroll
                for (int j = 0; j < 2; j++) bh[ni][j] = tf32_hi(br[ni][j]);

            // hi * hi
            #pragma unroll
            for (int mi = 0; mi < 4; mi++)
                #pragma unroll
                for (int ni = 0; ni < 4; ni++) mma8(acc[mi][ni], ah[mi], bh[ni]);

            // hi * lo
            uint32_t bl[4][2];
            #pragma unroll
            for (int ni = 0; ni < 4; ni++)
                #pragma unroll
                for (int j = 0; j < 2; j++) bl[ni][j] = tf32_lo(br[ni][j], bh[ni][j]);
            #pragma unroll
            for (int mi = 0; mi < 4; mi++)
                #pragma unroll
                for (int ni = 0; ni < 4; ni++) mma8(acc[mi][ni], ah[mi], bl[ni]);

            // lo * hi
            uint32_t al[4][4];
            #pragma unroll
            for (int mi = 0; mi < 4; mi++)
                #pragma unroll
                for (int j = 0; j < 4; j++) al[mi][j] = tf32_lo(ar[mi][j], ah[mi][j]);
            #pragma unroll
            for (int mi = 0; mi < 4; mi++)
                #pragma unroll
                for (int ni = 0; ni < 4; ni++) mma8(acc[mi][ni], al[mi], bh[ni]);
        }
        __syncthreads();
    }

    // epilogue: c0,c1 -> (row, col..col+1); c2,c3 -> (row+8, ...)
    const int er = lane >> 2, ec = (lane & 3) * 2;
    #pragma unroll
    for (int mi = 0; mi < 4; mi++) {
        long row = m0 + wm + mi * 16 + er;
        #pragma unroll
        for (int ni = 0; ni < 4; ni++) {
            long col = n0 + wn + ni * 8 + ec;
            *reinterpret_cast<float2*>(C + row * (long)N + col) =
                make_float2(acc[mi][ni][0], acc[mi][ni][1]);
            *reinterpret_cast<float2*>(C + (row + 8) * (long)N + col) =
                make_float2(acc[mi][ni][2], acc[mi][ni][3]);
        }
    }
}

// ---------------- xQ = x[b, 512, :] @ W_Q^T ----------------
__global__ void xq_kernel(const float* __restrict__ x, const float* __restrict__ WQ,
                          float* __restrict__ out_xq)
{
    int b = blockIdx.x;
    int w = threadIdx.x >> 5, lane = threadIdx.x & 31;
    int n = blockIdx.y * 8 + w;
    const float* xr = x + ((long)b * 513 + 512) * PD;
    const float* wr = WQ + (long)n * PD;
    float s = 0.f;
    for (int k = lane * 4; k < PD; k += 128) {
        float4 a = *reinterpret_cast<const float4*>(xr + k);
        float4 c = *reinterpret_cast<const float4*>(wr + k);
        s += a.x * c.x + a.y * c.y + a.z * c.z + a.w * c.w;
    }
    #pragma unroll
    for (int o = 16; o; o >>= 1) s += __shfl_down_sync(0xffffffffu, s, o);
    if (!lane) {
        g_xQ[b * PK + n] = s;
        out_xq[b * PK + n] = s;
    }
}

// ---------------- batched rowdot: out[b,r] = Rows[b,r,:]·xQ[b,:] (Kd=256) ----------------
__global__ void batched_dot(const float* __restrict__ Rows, long rStride,
                            float* __restrict__ outp, int oStride)
{
    int b = blockIdx.x;
    int w = threadIdx.x >> 5, lane = threadIdx.x & 31;
    int r = blockIdx.y * 8 + w;
    const float* row = Rows + (long)b * rStride + (long)r * PK;
    const float* v = g_xQ + b * PK;
    float s = 0.f;
    for (int k = lane * 4; k < PK; k += 128) {
        float4 a = *reinterpret_cast<const float4*>(row + k);
        float4 q = *reinterpret_cast<const float4*>(v + k);
        s += a.x * q.x + a.y * q.y + a.z * q.z + a.w * q.w;
    }
    #pragma unroll
    for (int o = 16; o; o >>= 1) s += __shfl_down_sync(0xffffffffu, s, o);
    if (!lane) outp[b * oStride + r] = s;
}

// ---------------- sequential one-winner scan (one block per batch) ----------------
__global__ void __launch_bounds__(256) scan_kernel()
{
    const int b = blockIdx.x, tid = threadIdx.x;
    __shared__ float grow[3][PT];
    __shared__ unsigned redm[2][8];
    __shared__ unsigned redh[2][8];

    const float* L0b = g_L0 + (size_t)b * PT * PH;
    const float* Gb  = g_G  + (size_t)b * PT * PT;

    int last[8];
    #pragma unroll
    for (int i = 0; i < 8; i++) last[i] = -1;

    float cur[8], n1[8];
    #pragma unroll
    for (int i = 0; i < 8; i++) cur[i] = L0b[i * 256 + tid];
    #pragma unroll
    for (int i = 0; i < 8; i++) n1[i] = L0b[PH + i * 256 + tid];
    grow[0][tid]       = Gb[tid];
    grow[0][256 + tid] = Gb[256 + tid];
    grow[1][tid]       = Gb[PT + tid];
    grow[1][256 + tid] = Gb[PT + 256 + tid];
    __syncthreads();

    const int lane = tid & 31, w = tid >> 5;
    int sc = 0, sw = 2;

    for (int t = 0; t < PT; t++) {
        float n2[8];
        if (t + 2 < PT) {
            const float* Lr = L0b + (size_t)(t + 2) * PH;
            #pragma unroll
            for (int i = 0; i < 8; i++) n2[i] = Lr[i * 256 + tid];
            const float* Gr = Gb + (size_t)(t + 2) * PT;
            float ga = Gr[tid], gb = Gr[256 + tid];
            grow[sw][tid]       = ga;
            grow[sw][256 + tid] = gb;
        }

        const float* gr = grow[sc];
        unsigned bestm;
        int besth;
        {
            float v = last[0] < 0 ? cur[0] : gr[last[0]];
            unsigned u = __float_as_uint(v);
            bestm = (u & 0x80000000u) ? ~u : (u | 0x80000000u);
            besth = tid;
        }
        #pragma unroll
        for (int i = 1; i < 8; i++) {
            float v = last[i] < 0 ? cur[i] : gr[last[i]];
            unsigned u = __float_as_uint(v);
            u = (u & 0x80000000u) ? ~u : (u | 0x80000000u);
            if (u > bestm) { bestm = u; besth = i * 256 + tid; }
        }
        unsigned m1 = __reduce_max_sync(0xffffffffu, bestm);
        unsigned hc = (bestm == m1) ? (unsigned)besth : 0xffffffffu;
        unsigned mh = __reduce_min_sync(0xffffffffu, hc);
        if (lane == 0) { redm[t & 1][w] = m1; redh[t & 1][w] = mh; }
        __syncthreads();

        unsigned bm = redm[t & 1][0], bh = redh[t & 1][0];
        #pragma unroll
        for (int j = 1; j < 8; j++) {
            unsigned m2 = redm[t & 1][j], h2 = redh[t & 1][j];
            if (m2 > bm || (m2 == bm && h2 < bh)) { bm = m2; bh = h2; }
        }
        if ((int)(bh & 255u) == tid) last[bh >> 8] = t;

        #pragma unroll
        for (int i = 0; i < 8; i++) { cur[i] = n1[i]; n1[i] = n2[i]; }
        sc = (sc == 2) ? 0 : sc + 1;
        sw = (sw == 2) ? 0 : sw + 1;
    }

    #pragma unroll
    for (int i = 0; i < 8; i++) g_last[b * PH + i * 256 + tid] = last[i];
}

// ---------------- softmax over final logits; split weights wt / wv ----------------
__global__ void softmax_kernel()
{
    int b = blockIdx.x, tid = threadIdx.x;
    __shared__ float red[8];

    g_wv[b * PT + tid]       = 0.f;
    g_wv[b * PT + 256 + tid] = 0.f;

    float l[8]; int ls[8];
    float mx = -3.4e38f;
    #pragma unroll
    for (int i = 0; i < 8; i++) {
        int h = i * 256 + tid;
        int t = g_last[b * PH + h];
        ls[i] = t;
        l[i] = (t < 0) ? g_q0[b * PH + h] : g_qk[b * PT + t];
        mx = fmaxf(mx, l[i]);
    }
    int lane = tid & 31, w = tid >> 5;
    #pragma unroll
    for (int o = 16; o; o >>= 1) mx = fmaxf(mx, __shfl_xor_sync(0xffffffffu, mx, o));
    if (!lane) red[w] = mx;
    __syncthreads();
    mx = red[0];
    #pragma unroll
    for (int j = 1; j < 8; j++) mx = fmaxf(mx, red[j]);

    float s = 0.f;
    #pragma unroll
    for (int i = 0; i < 8; i++) { l[i] = expf(l[i] - mx); s += l[i]; }
    #pragma unroll
    for (int o = 16; o; o >>= 1) s += __shfl_xor_sync(0xffffffffu, s, o);
    __syncthreads();
    if (!lane) red[w] = s;
    __syncthreads();
    s = 0.f;
    #pragma unroll
    for (int j = 0; j < 8; j++) s += red[j];

    float inv = 1.f / s;
    #pragma unroll
    for (int i = 0; i < 8; i++) {
        int h = i * 256 + tid;
        float wgt = l[i] * inv;
        if (ls[i] < 0) {
            g_wt[b * PH + h] = wgt;
        } else {
            g_wt[b * PH + h] = 0.f;
            g_wv[b * PT + ls[i]] = wgt;
        }
    }
}

// ---------------- reinst[b,d] = sum_h wt[h]*W_reinst0[b,h,d] + ybar[b,d]; writes ybar ----------------
__global__ void __launch_bounds__(256) reinst_kernel(
    const float* __restrict__ W_reinst0, const float* __restrict__ x, float* __restrict__ outp)
{
    int b = blockIdx.x, tid = threadIdx.x;
    int d0 = blockIdx.y * 256;
    __shared__ float wt_s[PH];
    __shared__ float wv_s[PT];
    #pragma unroll
    for (int i = 0; i < 8; i++) wt_s[i * 256 + tid] = g_wt[b * PH + i * 256 + tid];
    wv_s[tid]       = g_wv[b * PT + tid];
    wv_s[256 + tid] = g_wv[b * PT + 256 + tid];
    __syncthreads();

    float yb = 0.f;
    const float* xb = x + (size_t)b * 513 * PD + d0 + tid;
    #pragma unroll 8
    for (int t = 0; t < PT; t++) yb += wv_s[t] * xb[(size_t)t * PD];

    float acc = yb;
    const float* Wb = W_reinst0 + (size_t)b * PH * PD + d0 + tid;
    #pragma unroll 8
    for (int h = 0; h < PH; h++) acc += wt_s[h] * Wb[(size_t)h * PD];

    g_ybar[b * PD + d0 + tid] = yb;
    outp[b * PD + d0 + tid] = acc;
}

// ---------------- mhn[b,v] = W_oh0[b,v,:]@wt + W_V[v,:]@ybar  (grid: B x 8) ----------------
__global__ void __launch_bounds__(256) mhn_kernel(
    const float* __restrict__ W_oh0, const float* __restrict__ W_V)
{
    int b = blockIdx.x, tid = threadIdx.x, lane = tid & 31, w = tid >> 5;
    int v0 = blockIdx.y * 32;
    __shared__ float wt_s[PH];
    __shared__ float yb_s[PD];

    #pragma unroll
    for (int i = 0; i < 8; i++) wt_s[i * 256 + tid] = g_wt[b * PH + i * 256 + tid];
    #pragma unroll
    for (int i = 0; i < 4; i++) yb_s[i * 256 + tid] = g_ybar[b * PD + i * 256 + tid];
    __syncthreads();

    for (int pass = 0; pass < 4; pass++) {
        int v = v0 + pass * 8 + w;
        const float* row = W_oh0 + ((long)b * PV + v) * PH;
        float s = 0.f;
        #pragma unroll 4
        for (int h = lane * 4; h < PH; h += 128) {
            float4 a = *reinterpret_cast<const float4*>(row + h);
            s += a.x * wt_s[h] + a.y * wt_s[h + 1] + a.z * wt_s[h + 2] + a.w * wt_s[h + 3];
        }
        const float* wvr = W_V + (long)v * PD;
        #pragma unroll 4
        for (int d = lane * 4; d < PD; d += 128) {
            float4 a = *reinterpret_cast<const float4*>(wvr + d);
            s += a.x * yb_s[d] + a.y * yb_s[d + 1] + a.z * yb_s[d + 2] + a.w * yb_s[d + 3];
        }
        #pragma unroll
        for (int o = 16; o; o >>= 1) s += __shfl_down_sync(0xffffffffu, s, o);
        if (!lane) g_mhn[b * PV + v] = s;
    }
}

// ---------------- out[b,o] = mhn[b,:]@W_proj[o,:]  (grid: B x 8) ----------------
__global__ void __launch_bounds__(256) proj_kernel(
    const float* __restrict__ W_proj, float* __restrict__ outp)
{
    int b = blockIdx.x, tid = threadIdx.x, lane = tid & 31, w = tid >> 5;
    int o0 = blockIdx.y * 32;
    __shared__ float mhn_s[PV];
    if (tid < PV) mhn_s[tid] = g_mhn[b * PV + tid];
    __syncthreads();

    for (int pass = 0; pass < 4; pass++) {
        int o = o0 + pass * 8 + w;
        const float* pr = W_proj + (long)o * PV;
        float s = 0.f;
        for (int vv = lane * 4; vv < PV; vv += 128) {
            float4 a = *reinterpret_cast<const float4*>(pr + vv);
            s += a.x * mhn_s[vv] + a.y * mhn_s[vv + 1] + a.z * mhn_s[vv + 2] + a.w * mhn_s[vv + 3];
        }
        #pragma unroll
        for (int oo = 16; oo; oo >>= 1) s += __shfl_down_sync(0xffffffffu, s, oo);
        if (!lane) outp[b * PO + o] = s;
    }
}

// ---------------- launch ----------------
extern "C" void kernel_launch(void* const* d_in, const int* in_sizes, int n_in,
                              void* d_out, int out_size)
{
    const float* x         = (const float*)d_in[0];
    const float* W_Q       = (const float*)d_in[1];
    const float* W_K       = (const float*)d_in[2];
    const float* W_V       = (const float*)d_in[3];
    const float* W_proj    = (const float*)d_in[4];
    const float* W_hi0     = (const float*)d_in[5];
    const float* W_oh0     = (const float*)d_in[6];
    const float* W_reinst0 = (const float*)d_in[7];
    float* out = (float*)d_out;

    float *pxK, *pL0, *pG, *pq0, *pqk;
    cudaGetSymbolAddress((void**)&pxK, g_xK);
    cudaGetSymbolAddress((void**)&pL0, g_L0);
    cudaGetSymbolAddress((void**)&pG,  g_G);
    cudaGetSymbolAddress((void**)&pq0, g_q0);
    cudaGetSymbolAddress((void**)&pqk, g_qk);

    // output layout: [out 32x256 | reinst 32x1024 | xQ 32x256]
    float* out_main   = out;
    float* out_reinst = out + PB * PO;
    float* out_xq     = out + PB * PO + PB * PD;

    // 1) xK = ctx @ W_K^T  (M=16384, N=256, K=1024; ASKIP skips query rows)
    gemm_mma<true><<<dim3(2, 128, 1), 256>>>(x, W_K, pxK, PK, PD, 0, 0, 0);

    // 2) xQ
    xq_kernel<<<dim3(PB, PK / 8), 256>>>(x, W_Q, out_xq);

    // 3) L0[b,t,h] = xK[b,t]·W_hi0[b,h]   (per-batch M=512, N=2048, K=256)
    gemm_mma<false><<<dim3(16, 4, PB), 256>>>(pxK, W_hi0, pL0, PH, PK,
                                              (long)PT * PK, (long)PH * PK, (long)PT * PH);

    // 4) G[b,t,t'] = xK[b,t]·xK[b,t']     (per-batch M=N=512, K=256)
    gemm_mma<false><<<dim3(4, 4, PB), 256>>>(pxK, pxK, pG, PT, PK,
                                             (long)PT * PK, (long)PT * PK, (long)PT * PT);

    // 5) final logit pieces
    batched_dot<<<dim3(PB, PH / 8), 256>>>(W_hi0, (long)PH * PK, pq0, PH);
    batched_dot<<<dim3(PB, PT / 8), 256>>>(pxK, (long)PT * PK, pqk, PT);

    // 6) sequential winner scan
    scan_kernel<<<PB, 256>>>();

    // 7) softmax + weight split
    softmax_kernel<<<PB, 256>>>();

    // 8) outputs
    reinst_kernel<<<dim3(PB, PD / 256), 256>>>(W_reinst0, x, out_reinst);
    mhn_kernel<<<dim3(PB, 8), 256>>>(W_oh0, W_V);
    proj_kernel<<<dim3(PB, 8), 256>>>(W_proj, out_main);
}

// round 10
// speedup vs baseline: 1.7306x; 1.2069x over previous
#include <cuda_runtime.h>
#include <cstdint>
#include <cmath>

// Problem dims: B=32, S=513 (T=512 ctx + 1 query), D=1024, K=256, V=256, H=2048, O=256
#define PB 32
#define PT 512
#define PD 1024
#define PK 256
#define PV 256
#define PH 2048
#define PO 256

// ---------------- device scratch ----------------
__device__ float g_xK [(size_t)PB * PT * PK];           // 16 MB raw fp32
__device__ float g_xKh[(size_t)PB * PT * PK];           // 16 MB tf32-hi
__device__ float g_xKl[(size_t)PB * PT * PK];           // 16 MB tf32-lo
__device__ float g_xQ[PB * PK];
__device__ float g_L0[(size_t)PB * PT * PH];            // 128 MB
__device__ float g_G [(size_t)PB * PT * PT];            // 32 MB
__device__ int   g_last[PB * PH];
__device__ float g_q0[PB * PH];
__device__ float g_qk[PB * PT];
__device__ float g_wt[PB * PH];
__device__ float g_wv[PB * PT];
__device__ float g_ybar[PB * PD];
__device__ float g_mhn[PB * PV];
__device__ float g_rpart[4 * PB * PD];                  // reinst h-split partials

// ================= mma.sync tf32 helpers (NOT arch-variant-gated) =================
__device__ __forceinline__ uint32_t smem_u32(const void* p) {
    uint32_t a;
    asm("{ .reg .u64 t; cvta.to.shared.u64 t, %1; cvt.u32.u64 %0, t; }" : "=r"(a) : "l"(p));
    return a;
}
__device__ __forceinline__ uint32_t tf32_hi(uint32_t raw) {
    uint32_t u;
    asm("cvt.rna.tf32.f32 %0, %1;" : "=r"(u) : "f"(__uint_as_float(raw)));
    return u;
}
__device__ __forceinline__ uint32_t tf32_lo(uint32_t raw, uint32_t hi) {
    float d = __uint_as_float(raw) - __uint_as_float(hi);
    uint32_t u;
    asm("cvt.rna.tf32.f32 %0, %1;" : "=r"(u) : "f"(d));
    return u;
}
__device__ __forceinline__ void ldmx4(uint32_t* r, uint32_t addr) {
    asm volatile("ldmatrix.sync.aligned.m8n8.x4.shared.b16 {%0,%1,%2,%3}, [%4];"
                 : "=r"(r[0]), "=r"(r[1]), "=r"(r[2]), "=r"(r[3]) : "r"(addr));
}
__device__ __forceinline__ void ldmx2(uint32_t* r, uint32_t addr) {
    asm volatile("ldmatrix.sync.aligned.m8n8.x2.shared.b16 {%0,%1}, [%2];"
                 : "=r"(r[0]), "=r"(r[1]) : "r"(addr));
}
__device__ __forceinline__ void mma8(float* c, const uint32_t* a, const uint32_t* b) {
    asm volatile(
        "mma.sync.aligned.m16n8k8.row.col.f32.tf32.tf32.f32 "
        "{%0,%1,%2,%3}, {%4,%5,%6,%7}, {%8,%9}, {%0,%1,%2,%3};"
        : "+f"(c[0]), "+f"(c[1]), "+f"(c[2]), "+f"(c[3])
        : "r"(a[0]), "r"(a[1]), "r"(a[2]), "r"(a[3]), "r"(b[0]), "r"(b[1]));
}
__device__ __forceinline__ void cp16(uint32_t dst, const void* src) {
    asm volatile("cp.async.ca.shared.global [%0], [%1], 16;" :: "r"(dst), "l"(src) : "memory");
}
__device__ __forceinline__ void cp_commit() {
    asm volatile("cp.async.commit_group;" ::: "memory");
}
__device__ __forceinline__ void cp_wait3() {
    asm volatile("cp.async.wait_group 3;" ::: "memory");
}
__device__ __forceinline__ void cp_wait1() {
    asm volatile("cp.async.wait_group 1;" ::: "memory");
}
__device__ __forceinline__ void cp_wait0() {
    asm volatile("cp.async.wait_group 0;" ::: "memory");
}

#define TSTRIDE 20                     // floats per smem row (16 data + 4 pad)
#define TILE_F (128 * TSTRIDE)

// ================= GEMM 1: fp32 in, cvt in-register (used for xK only) =================
// Also emits tf32 hi/lo copies of C for downstream pre-split GEMMs.
__global__ void __launch_bounds__(256) gemm_mma(
    const float* __restrict__ Ag, const float* __restrict__ Bg,
    float* __restrict__ Cg, float* __restrict__ Ch, float* __restrict__ Cl,
    int N, int Kd)
{
    __shared__ __align__(16) float smA[2][TILE_F];
    __shared__ __align__(16) float smB[2][TILE_F];

    const float* A = Ag;
    const float* B = Bg;
    const int m0 = blockIdx.y * 128;
    const int n0 = blockIdx.x * 128;
    const int tid = threadIdx.x, wid = tid >> 5, lane = tid & 31;
    const int wm = (wid & 1) * 64;
    const int wn = (wid >> 1) * 32;

    float acc[4][4][4];
    #pragma unroll
    for (int i = 0; i < 4; i++)
        #pragma unroll
        for (int j = 0; j < 4; j++)
            #pragma unroll
            for (int k = 0; k < 4; k++) acc[i][j][k] = 0.f;

    const int p_row0 = tid >> 2, p_q0 = tid & 3;
    const int p_row1 = (tid + 256) >> 2;

    const uint32_t sa0 = smem_u32(smA[0]);
    const uint32_t sb0 = smem_u32(smB[0]);

    const int a_r = (lane & 7) + ((lane >> 3) & 1) * 8;
    const int a_c = (lane >> 4) * 4;
    const int b_r = (lane & 7);
    const int b_c = ((lane >> 3) & 1) * 4;
    const uint32_t aOff = (uint32_t)(((wm + a_r) * TSTRIDE + a_c) * 4);
    const uint32_t bOff = (uint32_t)(((wn + b_r) * TSTRIDE + b_c) * 4);

    const int nc = Kd >> 4;

    auto issue = [&](int c, int bu) {
        const int k0 = c * 16;
        {
            long am = (long)(m0 + p_row0);
            long ar = am + (am >> 9);          // skip query rows
            cp16(sa0 + (uint32_t)((bu * TILE_F + p_row0 * TSTRIDE + p_q0 * 4) * 4),
                 A + ar * (long)Kd + k0 + p_q0 * 4);
            cp16(sb0 + (uint32_t)((bu * TILE_F + p_row0 * TSTRIDE + p_q0 * 4) * 4),
                 B + (long)(n0 + p_row0) * Kd + k0 + p_q0 * 4);
        }
        {
            long am = (long)(m0 + p_row1);
            long ar = am + (am >> 9);
            cp16(sa0 + (uint32_t)((bu * TILE_F + p_row1 * TSTRIDE + p_q0 * 4) * 4),
                 A + ar * (long)Kd + k0 + p_q0 * 4);
            cp16(sb0 + (uint32_t)((bu * TILE_F + p_row1 * TSTRIDE + p_q0 * 4) * 4),
                 B + (long)(n0 + p_row1) * Kd + k0 + p_q0 * 4);
        }
        cp_commit();
    };

    issue(0, 0);
    for (int c = 0; c < nc; c++) {
        const int bu = c & 1;
        if (c + 1 < nc) { issue(c + 1, bu ^ 1); cp_wait1(); }
        else            { cp_wait0(); }
        __syncthreads();

        const uint32_t aB = sa0 + (uint32_t)(bu * TILE_F * 4) + aOff;
        const uint32_t bB = sb0 + (uint32_t)(bu * TILE_F * 4) + bOff;

        #pragma unroll
        for (int k8 = 0; k8 < 2; k8++) {
            uint32_t ar[4][4], br[4][2];
            #pragma unroll
            for (int mi = 0; mi < 4; mi++)
                ldmx4(ar[mi], aB + (uint32_t)((mi * 16 * TSTRIDE) * 4 + k8 * 32));
            #pragma unroll
            for (int ni = 0; ni < 4; ni++)
                ldmx2(br[ni], bB + (uint32_t)((ni * 8 * TSTRIDE) * 4 + k8 * 32));

            uint32_t ah[4][4], bh[4][2];
            #pragma unroll
            for (int mi = 0; mi < 4; mi++)
                #pragma unroll
                for (int j = 0; j < 4; j++) ah[mi][j] = tf32_hi(ar[mi][j]);
            #pragma unroll
            for (int ni = 0; ni < 4; ni++)
                #pragma unroll
                for (int j = 0; j < 2; j++) bh[ni][j] = tf32_hi(br[ni][j]);

            #pragma unroll
            for (int mi = 0; mi < 4; mi++)
                #pragma unroll
                for (int ni = 0; ni < 4; ni++) mma8(acc[mi][ni], ah[mi], bh[ni]);

            uint32_t bl[4][2];
            #pragma unroll
            for (int ni = 0; ni < 4; ni++)
                #pragma unroll
                for (int j = 0; j < 2; j++) bl[ni][j] = tf32_lo(br[ni][j], bh[ni][j]);
            #pragma unroll
            for (int mi = 0; mi < 4; mi++)
                #pragma unroll
                for (int ni = 0; ni < 4; ni++) mma8(acc[mi][ni], ah[mi], bl[ni]);

            uint32_t al[4][4];
            #pragma unroll
            for (int mi = 0; mi < 4; mi++)
                #pragma unroll
                for (int j = 0; j < 4; j++) al[mi][j] = tf32_lo(ar[mi][j], ah[mi][j]);
            #pragma unroll
            for (int mi = 0; mi < 4; mi++)
                #pragma unroll
                for (int ni = 0; ni < 4; ni++) mma8(acc[mi][ni], al[mi], bh[ni]);
        }
        __syncthreads();
    }

    const int er = lane >> 2, ec = (lane & 3) * 2;
    #pragma unroll
    for (int mi = 0; mi < 4; mi++) {
        long row = m0 + wm + mi * 16 + er;
        #pragma unroll
        for (int ni = 0; ni < 4; ni++) {
            long col = n0 + wn + ni * 8 + ec;
            #pragma unroll
            for (int half = 0; half < 2; half++) {
                long off = (row + half * 8) * (long)N + col;
                float v0 = acc[mi][ni][half * 2 + 0];
                float v1 = acc[mi][ni][half * 2 + 1];
                *reinterpret_cast<float2*>(Cg + off) = make_float2(v0, v1);
                uint32_t h0 = tf32_hi(__float_as_uint(v0));
                uint32_t h1 = tf32_hi(__float_as_uint(v1));
                *reinterpret_cast<float2*>(Ch + off) =
                    make_float2(__uint_as_float(h0), __uint_as_float(h1));
                *reinterpret_cast<float2*>(Cl + off) =
                    make_float2(__uint_as_float(tf32_lo(__float_as_uint(v0), h0)),
                                __uint_as_float(tf32_lo(__float_as_uint(v1), h1)));
            }
        }
    }
}

// ================= GEMM 2: pre-split operands =================
// A always pre-split (Ah/Al). B pre-split if BSPLIT, else raw fp32 + in-register cvt.
// Dynamic smem: [Ahi x2][Alo x2][Bhi x2][Blo x2 (BSPLIT only)]
template <bool BSPLIT>
__global__ void __launch_bounds__(256) gemm_ps(
    const float* __restrict__ Ahg, const float* __restrict__ Alg,
    const float* __restrict__ Bhg, const float* __restrict__ Blg,
    float* __restrict__ Cg,
    int N, int Kd, long sA, long sB, long sC)
{
    extern __shared__ float sm[];
    const float* Ah = Ahg + (long)blockIdx.z * sA;
    const float* Al = Alg + (long)blockIdx.z * sA;
    const float* Bh = Bhg + (long)blockIdx.z * sB;
    const float* Bl = BSPLIT ? (Blg + (long)blockIdx.z * sB) : nullptr;
    float*       C  = Cg  + (long)blockIdx.z * sC;

    const int m0 = blockIdx.y * 128;
    const int n0 = blockIdx.x * 128;
    const int tid = threadIdx.x, wid = tid >> 5, lane = tid & 31;
    const int wm = (wid & 1) * 64;
    const int wn = (wid >> 1) * 32;

    const uint32_t sbase = smem_u32(sm);
    const uint32_t OAH = 0, OAL = 2 * TILE_F, OBH = 4 * TILE_F, OBL = 6 * TILE_F;

    float acc[4][4][4];
    #pragma unroll
    for (int i = 0; i < 4; i++)
        #pragma unroll
        for (int j = 0; j < 4; j++)
            #pragma unroll
            for (int k = 0; k < 4; k++) acc[i][j][k] = 0.f;

    const int p_row0 = tid >> 2, p_q0 = tid & 3;
    const int p_row1 = (tid + 256) >> 2;

    const int a_r = (lane & 7) + ((lane >> 3) & 1) * 8;
    const int a_c = (lane >> 4) * 4;
    const int b_r = (lane & 7);
    const int b_c = ((lane >> 3) & 1) * 4;
    const uint32_t aOff = (uint32_t)(((wm + a_r) * TSTRIDE + a_c) * 4);
    const uint32_t bOff = (uint32_t)(((wn + b_r) * TSTRIDE + b_c) * 4);

    const int nc = Kd >> 4;

    auto issue = [&](int c, int bu) {
        const int k0 = c * 16;
        #pragma unroll
        for (int h = 0; h < 2; h++) {
            const int pr = h ? p_row1 : p_row0;
            const uint32_t dof = (uint32_t)((bu * TILE_F + pr * TSTRIDE + p_q0 * 4) * 4);
            const long aoff = (long)(m0 + pr) * Kd + k0 + p_q0 * 4;
            const long boff = (long)(n0 + pr) * Kd + k0 + p_q0 * 4;
            cp16(sbase + OAH * 4 + dof, Ah + aoff);
            cp16(sbase + OAL * 4 + dof, Al + aoff);
            cp16(sbase + OBH * 4 + dof, Bh + boff);
            if (BSPLIT) cp16(sbase + OBL * 4 + dof, Bl + boff);
        }
        cp_commit();
    };

    issue(0, 0);
    for (int c = 0; c < nc; c++) {
        const int bu = c & 1;
        if (c + 1 < nc) { issue(c + 1, bu ^ 1); cp_wait1(); }
        else            { cp_wait0(); }
        __syncthreads();

        const uint32_t bufo = (uint32_t)(bu * TILE_F * 4);
        const uint32_t aH = sbase + OAH * 4 + bufo + aOff;
        const uint32_t aL = sbase + OAL * 4 + bufo + aOff;
        const uint32_t bH = sbase + OBH * 4 + bufo + bOff;
        const uint32_t bL = sbase + OBL * 4 + bufo + bOff;

        #pragma unroll
        for (int k8 = 0; k8 < 2; k8++) {
            uint32_t ah[4][4], al[4][4], bh[4][2], bl[4][2];
            #pragma unroll
            for (int mi = 0; mi < 4; mi++) {
                const uint32_t o = (uint32_t)((mi * 16 * TSTRIDE) * 4 + k8 * 32);
                ldmx4(ah[mi], aH + o);
                ldmx4(al[mi], aL + o);
            }
            if (BSPLIT) {
                #pragma unroll
                for (int ni = 0; ni < 4; ni++) {
                    const uint32_t o = (uint32_t)((ni * 8 * TSTRIDE) * 4 + k8 * 32);
                    ldmx2(bh[ni], bH + o);
                    ldmx2(bl[ni], bL + o);
                }
            } else {
                #pragma unroll
                for (int ni = 0; ni < 4; ni++) {
                    uint32_t br[2];
                    ldmx2(br, bH + (uint32_t)((ni * 8 * TSTRIDE) * 4 + k8 * 32));
                    bh[ni][0] = tf32_hi(br[0]);
                    bh[ni][1] = tf32_hi(br[1]);
                    bl[ni][0] = tf32_lo(br[0], bh[ni][0]);
                    bl[ni][1] = tf32_lo(br[1], bh[ni][1]);
                }
            }

            #pragma unroll
            for (int mi = 0; mi < 4; mi++)
                #pragma unroll
                for (int ni = 0; ni < 4; ni++) mma8(acc[mi][ni], ah[mi], bh[ni]);
            #pragma unroll
            for (int mi = 0; mi < 4; mi++)
                #pragma unroll
                for (int ni = 0; ni < 4; ni++) mma8(acc[mi][ni], ah[mi], bl[ni]);
            #pragma unroll
            for (int mi = 0; mi < 4; mi++)
                #pragma unroll
                for (int ni = 0; ni < 4; ni++) mma8(acc[mi][ni], al[mi], bh[ni]);
        }
        __syncthreads();
    }

    const int er = lane >> 2, ec = (lane & 3) * 2;
    #pragma unroll
    for (int mi = 0; mi < 4; mi++) {
        long row = m0 + wm + mi * 16 + er;
        #pragma unroll
        for (int ni = 0; ni < 4; ni++) {
            long col = n0 + wn + ni * 8 + ec;
            *reinterpret_cast<float2*>(C + row * (long)N + col) =
                make_float2(acc[mi][ni][0], acc[mi][ni][1]);
            *reinterpret_cast<float2*>(C + (row + 8) * (long)N + col) =
                make_float2(acc[mi][ni][2], acc[mi][ni][3]);
        }
    }
}

// ---------------- xQ = x[b, 512, :] @ W_Q^T ----------------
__global__ void xq_kernel(const float* __restrict__ x, const float* __restrict__ WQ,
                          float* __restrict__ out_xq)
{
    int b = blockIdx.x;
    int w = threadIdx.x >> 5, lane = threadIdx.x & 31;
    int n = blockIdx.y * 8 + w;
    const float* xr = x + ((long)b * 513 + 512) * PD;
    const float* wr = WQ + (long)n * PD;
    float s = 0.f;
    for (int k = lane * 4; k < PD; k += 128) {
        float4 a = *reinterpret_cast<const float4*>(xr + k);
        float4 c = *reinterpret_cast<const float4*>(wr + k);
        s += a.x * c.x + a.y * c.y + a.z * c.z + a.w * c.w;
    }
    #pragma unroll
    for (int o = 16; o; o >>= 1) s += __shfl_down_sync(0xffffffffu, s, o);
    if (!lane) {
        g_xQ[b * PK + n] = s;
        out_xq[b * PK + n] = s;
    }
}

// ---------------- batched rowdot: out[b,r] = Rows[b,r,:]·xQ[b,:] (Kd=256) ----------------
__global__ void batched_dot(const float* __restrict__ Rows, long rStride,
                            float* __restrict__ outp, int oStride)
{
    int b = blockIdx.x;
    int w = threadIdx.x >> 5, lane = threadIdx.x & 31;
    int r = blockIdx.y * 8 + w;
    const float* row = Rows + (long)b * rStride + (long)r * PK;
    const float* v = g_xQ + b * PK;
    float s = 0.f;
    for (int k = lane * 4; k < PK; k += 128) {
        float4 a = *reinterpret_cast<const float4*>(row + k);
        float4 q = *reinterpret_cast<const float4*>(v + k);
        s += a.x * q.x + a.y * q.y + a.z * q.z + a.w * q.w;
    }
    #pragma unroll
    for (int o = 16; o; o >>= 1) s += __shfl_down_sync(0xffffffffu, s, o);
    if (!lane) outp[b * oStride + r] = s;
}

// ---------------- sequential one-winner scan: cp.async depth-5 ring ----------------
// Ring depth 5 with prefetch distance 4: writer targets slot (t+4)%5, readers use
// slot t%5 — never the same slot, so one barrier per step is race-free.
__global__ void __launch_bounds__(256) scan_kernel()
{
    const int b = blockIdx.x, tid = threadIdx.x;
    __shared__ __align__(16) float L0s[5][PH];   // 40 KB ring
    __shared__ __align__(16) float Gs[5][PT];    // 10 KB ring
    __shared__ unsigned redm[2][8];
    __shared__ unsigned redh[2][8];

    const float* L0b = g_L0 + (size_t)b * PT * PH;
    const float* Gb  = g_G  + (size_t)b * PT * PT;
    const uint32_t sL = smem_u32(L0s);
    const uint32_t sG = smem_u32(Gs);

    int last[8];
    #pragma unroll
    for (int i = 0; i < 8; i++) last[i] = -1;

    auto issue_row = [&](int r) {
        const int sl = r % 5;
        cp16(sL + (uint32_t)((sl * PH + tid * 4) * 4),         L0b + (size_t)r * PH + tid * 4);
        cp16(sL + (uint32_t)((sl * PH + (tid + 256) * 4) * 4), L0b + (size_t)r * PH + (tid + 256) * 4);
        if (tid < 128)
            cp16(sG + (uint32_t)((sl * PT + tid * 4) * 4),     Gb + (size_t)r * PT + tid * 4);
    };

    #pragma unroll
    for (int r = 0; r < 4; r++) { issue_row(r); cp_commit(); }
    cp_wait3();
    __syncthreads();

    const int lane = tid & 31, w = tid >> 5;
    int slot = 0;

    for (int t = 0; t < PT; t++) {
        const float* gr = Gs[slot];
        const float* lr = L0s[slot];

        unsigned bestm;
        int besth;
        {
            float v = last[0] < 0 ? lr[tid] : gr[last[0]];
            unsigned u = __float_as_uint(v);
            bestm = (u & 0x80000000u) ? ~u : (u | 0x80000000u);
            besth = tid;
        }
        #pragma unroll
        for (int i = 1; i < 8; i++) {
            float v = last[i] < 0 ? lr[i * 256 + tid] : gr[last[i]];
            unsigned u = __float_as_uint(v);
            u = (u & 0x80000000u) ? ~u : (u | 0x80000000u);
            if (u > bestm) { bestm = u; besth = i * 256 + tid; }
        }
        unsigned m1 = __reduce_max_sync(0xffffffffu, bestm);
        unsigned hc = (bestm == m1) ? (unsigned)besth : 0xffffffffu;
        unsigned mh = __reduce_min_sync(0xffffffffu, hc);
        if (lane == 0) { redm[t & 1][w] = m1; redh[t & 1][w] = mh; }

        // prefetch row t+4 into slot (t+4)%5 (disjoint from any slot being read)
        if (t + 4 < PT) issue_row(t + 4);
        cp_commit();
        cp_wait3();
        __syncthreads();

        unsigned bm = redm[t & 1][0], bh = redh[t & 1][0];
        #pragma unroll
        for (int j = 1; j < 8; j++) {
            unsigned m2 = redm[t & 1][j], h2 = redh[t & 1][j];
            if (m2 > bm || (m2 == bm && h2 < bh)) { bm = m2; bh = h2; }
        }
        if ((int)(bh & 255u) == tid) last[bh >> 8] = t;

        slot = (slot == 4) ? 0 : slot + 1;
    }

    #pragma unroll
    for (int i = 0; i < 8; i++) g_last[b * PH + i * 256 + tid] = last[i];
}

// ---------------- softmax over final logits; split weights wt / wv ----------------
__global__ void softmax_kernel()
{
    int b = blockIdx.x, tid = threadIdx.x;
    __shared__ float red[8];

    g_wv[b * PT + tid]       = 0.f;
    g_wv[b * PT + 256 + tid] = 0.f;

    float l[8]; int ls[8];
    float mx = -3.4e38f;
    #pragma unroll
    for (int i = 0; i < 8; i++) {
        int h = i * 256 + tid;
        int t = g_last[b * PH + h];
        ls[i] = t;
        l[i] = (t < 0) ? g_q0[b * PH + h] : g_qk[b * PT + t];
        mx = fmaxf(mx, l[i]);
    }
    int lane = tid & 31, w = tid >> 5;
    #pragma unroll
    for (int o = 16; o; o >>= 1) mx = fmaxf(mx, __shfl_xor_sync(0xffffffffu, mx, o));
    if (!lane) red[w] = mx;
    __syncthreads();
    mx = red[0];
    #pragma unroll
    for (int j = 1; j < 8; j++) mx = fmaxf(mx, red[j]);

    float s = 0.f;
    #pragma unroll
    for (int i = 0; i < 8; i++) { l[i] = expf(l[i] - mx); s += l[i]; }
    #pragma unroll
    for (int o = 16; o; o >>= 1) s += __shfl_xor_sync(0xffffffffu, s, o);
    __syncthreads();
    if (!lane) red[w] = s;
    __syncthreads();
    s = 0.f;
    #pragma unroll
    for (int j = 0; j < 8; j++) s += red[j];

    float inv = 1.f / s;
    #pragma unroll
    for (int i = 0; i < 8; i++) {
        int h = i * 256 + tid;
        float wgt = l[i] * inv;
        if (ls[i] < 0) {
            g_wt[b * PH + h] = wgt;
        } else {
            g_wt[b * PH + h] = 0.f;
            g_wv[b * PT + ls[i]] = wgt;
        }
    }
}

// ---------------- ybar[b,d] = sum_t wv[t]*x[b,t,d] ----------------
__global__ void __launch_bounds__(256) ybar_kernel(const float* __restrict__ x)
{
    int b = blockIdx.x, tid = threadIdx.x;
    int d0 = blockIdx.y * 256;
    __shared__ float wv_s[PT];
    wv_s[tid]       = g_wv[b * PT + tid];
    wv_s[256 + tid] = g_wv[b * PT + 256 + tid];
    __syncthreads();

    float yb = 0.f;
    const float* xb = x + (size_t)b * 513 * PD + d0 + tid;
    #pragma unroll 8
    for (int t = 0; t < PT; t++) yb += wv_s[t] * xb[(size_t)t * PD];
    g_ybar[b * PD + d0 + tid] = yb;
}

// ---------------- reinst partials: h-range split across blockIdx.z ----------------
__global__ void __launch_bounds__(256) reinst_part(const float* __restrict__ W_reinst0)
{
    int b = blockIdx.x, tid = threadIdx.x;
    int d0 = blockIdx.y * 256;
    int z = blockIdx.z;
    __shared__ float wt_s[512];
    wt_s[tid]       = g_wt[b * PH + z * 512 + tid];
    wt_s[256 + tid] = g_wt[b * PH + z * 512 + 256 + tid];
    __syncthreads();

    float acc = 0.f;
    const float* Wb = W_reinst0 + (size_t)b * PH * PD + (size_t)(z * 512) * PD + d0 + tid;
    #pragma unroll 8
    for (int h = 0; h < 512; h++) acc += wt_s[h] * Wb[(size_t)h * PD];
    g_rpart[((size_t)z * PB + b) * PD + d0 + tid] = acc;
}

__global__ void __launch_bounds__(256) reinst_reduce(float* __restrict__ outp)
{
    int b = blockIdx.x, tid = threadIdx.x;
    int d = blockIdx.y * 256 + tid;
    float s = g_ybar[b * PD + d];
    #pragma unroll
    for (int z = 0; z < 4; z++) s += g_rpart[((size_t)z * PB + b) * PD + d];
    outp[b * PD + d] = s;
}

// ---------------- mhn[b,v] = W_oh0[b,v,:]@wt + W_V[v,:]@ybar  (grid: B x 8) ----------------
__global__ void __launch_bounds__(256) mhn_kernel(
    const float* __restrict__ W_oh0, const float* __restrict__ W_V)
{
    int b = blockIdx.x, tid = threadIdx.x, lane = tid & 31, w = tid >> 5;
    int v0 = blockIdx.y * 32;
    __shared__ float wt_s[PH];
    __shared__ float yb_s[PD];

    #pragma unroll
    for (int i = 0; i < 8; i++) wt_s[i * 256 + tid] = g_wt[b * PH + i * 256 + tid];
    #pragma unroll
    for (int i = 0; i < 4; i++) yb_s[i * 256 + tid] = g_ybar[b * PD + i * 256 + tid];
    __syncthreads();

    for (int pass = 0; pass < 4; pass++) {
        int v = v0 + pass * 8 + w;
        const float* row = W_oh0 + ((long)b * PV + v) * PH;
        float s = 0.f;
        #pragma unroll 4
        for (int h = lane * 4; h < PH; h += 128) {
            float4 a = *reinterpret_cast<const float4*>(row + h);
            s += a.x * wt_s[h] + a.y * wt_s[h + 1] + a.z * wt_s[h + 2] + a.w * wt_s[h + 3];
        }
        const float* wvr = W_V + (long)v * PD;
        #pragma unroll 4
        for (int d = lane * 4; d < PD; d += 128) {
            float4 a = *reinterpret_cast<const float4*>(wvr + d);
            s += a.x * yb_s[d] + a.y * yb_s[d + 1] + a.z * yb_s[d + 2] + a.w * yb_s[d + 3];
        }
        #pragma unroll
        for (int o = 16; o; o >>= 1) s += __shfl_down_sync(0xffffffffu, s, o);
        if (!lane) g_mhn[b * PV + v] = s;
    }
}

// ---------------- out[b,o] = mhn[b,:]@W_proj[o,:]  (grid: B x 8) ----------------
__global__ void __launch_bounds__(256) proj_kernel(
    const float* __restrict__ W_proj, float* __restrict__ outp)
{
    int b = blockIdx.x, tid = threadIdx.x, lane = tid & 31, w = tid >> 5;
    int o0 = blockIdx.y * 32;
    __shared__ float mhn_s[PV];
    if (tid < PV) mhn_s[tid] = g_mhn[b * PV + tid];
    __syncthreads();

    for (int pass = 0; pass < 4; pass++) {
        int o = o0 + pass * 8 + w;
        const float* pr = W_proj + (long)o * PV;
        float s = 0.f;
        for (int vv = lane * 4; vv < PV; vv += 128) {
            float4 a = *reinterpret_cast<const float4*>(pr + vv);
            s += a.x * mhn_s[vv] + a.y * mhn_s[vv + 1] + a.z * mhn_s[vv + 2] + a.w * mhn_s[vv + 3];
        }
        #pragma unroll
        for (int oo = 16; oo; oo >>= 1) s += __shfl_down_sync(0xffffffffu, s, oo);
        if (!lane) outp[b * PO + o] = s;
    }
}

// ---------------- launch ----------------
extern "C" void kernel_launch(void* const* d_in, const int* in_sizes, int n_in,
                              void* d_out, int out_size)
{
    const float* x         = (const float*)d_in[0];
    const float* W_Q       = (const float*)d_in[1];
    const float* W_K       = (const float*)d_in[2];
    const float* W_V       = (const float*)d_in[3];
    const float* W_proj    = (const float*)d_in[4];
    const float* W_hi0     = (const float*)d_in[5];
    const float* W_oh0     = (const float*)d_in[6];
    const float* W_reinst0 = (const float*)d_in[7];
    float* out = (float*)d_out;

    float *pxK, *pxKh, *pxKl, *pL0, *pG, *pq0, *pqk;
    cudaGetSymbolAddress((void**)&pxK,  g_xK);
    cudaGetSymbolAddress((void**)&pxKh, g_xKh);
    cudaGetSymbolAddress((void**)&pxKl, g_xKl);
    cudaGetSymbolAddress((void**)&pL0,  g_L0);
    cudaGetSymbolAddress((void**)&pG,   g_G);
    cudaGetSymbolAddress((void**)&pq0,  g_q0);
    cudaGetSymbolAddress((void**)&pqk,  g_qk);

    const int SM_L0 = 6 * TILE_F * 4;   // 61440
    const int SM_G  = 8 * TILE_F * 4;   // 81920
    cudaFuncSetAttribute((const void*)gemm_ps<false>,
                         cudaFuncAttributeMaxDynamicSharedMemorySize, SM_L0);
    cudaFuncSetAttribute((const void*)gemm_ps<true>,
                         cudaFuncAttributeMaxDynamicSharedMemorySize, SM_G);

    // output layout: [out 32x256 | reinst 32x1024 | xQ 32x256]
    float* out_main   = out;
    float* out_reinst = out + PB * PO;
    float* out_xq     = out + PB * PO + PB * PD;

    // 1) xK = ctx @ W_K^T (+ tf32 hi/lo copies)
    gemm_mma<<<dim3(2, 128, 1), 256>>>(x, W_K, pxK, pxKh, pxKl, PK, PD);

    // 2) xQ
    xq_kernel<<<dim3(PB, PK / 8), 256>>>(x, W_Q, out_xq);

    // 3) L0[b,t,h] = xK[b,t]·W_hi0[b,h]  (A pre-split, B raw)
    gemm_ps<false><<<dim3(16, 4, PB), 256, SM_L0>>>(pxKh, pxKl, W_hi0, nullptr, pL0,
                                                    PH, PK,
                                                    (long)PT * PK, (long)PH * PK, (long)PT * PH);

    // 4) G[b,t,t'] = xK[b,t]·xK[b,t']    (both pre-split)
    gemm_ps<true><<<dim3(4, 4, PB), 256, SM_G>>>(pxKh, pxKl, pxKh, pxKl, pG,
                                                 PT, PK,
                                                 (long)PT * PK, (long)PT * PK, (long)PT * PT);

    // 5) final logit pieces
    batched_dot<<<dim3(PB, PH / 8), 256>>>(W_hi0, (long)PH * PK, pq0, PH);
    batched_dot<<<dim3(PB, PT / 8), 256>>>(pxK, (long)PT * PK, pqk, PT);

    // 6) sequential winner scan
    scan_kernel<<<PB, 256>>>();

    // 7) softmax + weight split
    softmax_kernel<<<PB, 256>>>();

    // 8) outputs
    ybar_kernel<<<dim3(PB, PD / 256), 256>>>(x);
    reinst_part<<<dim3(PB, PD / 256, 4), 256>>>(W_reinst0);
    reinst_reduce<<<dim3(PB, PD / 256), 256>>>(out_reinst);
    mhn_kernel<<<dim3(PB, 8), 256>>>(W_oh0, W_V);
    proj_kernel<<<dim3(PB, 8), 256>>>(W_proj, out_main);
}

// round 11
// speedup vs baseline: 1.8494x; 1.0686x over previous
#include <cuda_runtime.h>
#include <cstdint>
#include <cmath>

// Problem dims: B=32, S=513 (T=512 ctx + 1 query), D=1024, K=256, V=256, H=2048, O=256
#define PB 32
#define PT 512
#define PD 1024
#define PK 256
#define PV 256
#define PH 2048
#define PO 256

// ---------------- device scratch ----------------
__device__ float g_xKh[(size_t)PB * PT * PK];           // 16 MB tf32-hi
__device__ float g_xKl[(size_t)PB * PT * PK];           // 16 MB tf32-lo
__device__ float g_xQ[PB * PK];
__device__ float g_L0[(size_t)PB * PT * PH];            // 128 MB
__device__ float g_G [(size_t)PB * PT * PT];            // 32 MB (lower triangle valid)
__device__ float g_q0[PB * PH];
__device__ float g_qk[PB * PT];
__device__ float g_wt[PB * PH];
__device__ float g_wv[PB * PT];
__device__ float g_ybar[PB * PD];
__device__ float g_mhn[PB * PV];
__device__ float g_rpart[4 * PB * PD];                  // reinst h-split partials

// ================= mma.sync tf32 helpers (NOT arch-variant-gated) =================
__device__ __forceinline__ uint32_t smem_u32(const void* p) {
    uint32_t a;
    asm("{ .reg .u64 t; cvta.to.shared.u64 t, %1; cvt.u32.u64 %0, t; }" : "=r"(a) : "l"(p));
    return a;
}
__device__ __forceinline__ uint32_t tf32_hi(uint32_t raw) {
    uint32_t u;
    asm("cvt.rna.tf32.f32 %0, %1;" : "=r"(u) : "f"(__uint_as_float(raw)));
    return u;
}
__device__ __forceinline__ uint32_t tf32_lo(uint32_t raw, uint32_t hi) {
    float d = __uint_as_float(raw) - __uint_as_float(hi);
    uint32_t u;
    asm("cvt.rna.tf32.f32 %0, %1;" : "=r"(u) : "f"(d));
    return u;
}
__device__ __forceinline__ void ldmx4(uint32_t* r, uint32_t addr) {
    asm volatile("ldmatrix.sync.aligned.m8n8.x4.shared.b16 {%0,%1,%2,%3}, [%4];"
                 : "=r"(r[0]), "=r"(r[1]), "=r"(r[2]), "=r"(r[3]) : "r"(addr));
}
__device__ __forceinline__ void ldmx2(uint32_t* r, uint32_t addr) {
    asm volatile("ldmatrix.sync.aligned.m8n8.x2.shared.b16 {%0,%1}, [%2];"
                 : "=r"(r[0]), "=r"(r[1]) : "r"(addr));
}
__device__ __forceinline__ void mma8(float* c, const uint32_t* a, const uint32_t* b) {
    asm volatile(
        "mma.sync.aligned.m16n8k8.row.col.f32.tf32.tf32.f32 "
        "{%0,%1,%2,%3}, {%4,%5,%6,%7}, {%8,%9}, {%0,%1,%2,%3};"
        : "+f"(c[0]), "+f"(c[1]), "+f"(c[2]), "+f"(c[3])
        : "r"(a[0]), "r"(a[1]), "r"(a[2]), "r"(a[3]), "r"(b[0]), "r"(b[1]));
}
__device__ __forceinline__ void cp16(uint32_t dst, const void* src) {
    asm volatile("cp.async.ca.shared.global [%0], [%1], 16;" :: "r"(dst), "l"(src) : "memory");
}
__device__ __forceinline__ void cp_commit() {
    asm volatile("cp.async.commit_group;" ::: "memory");
}
__device__ __forceinline__ void cp_wait3() {
    asm volatile("cp.async.wait_group 3;" ::: "memory");
}
__device__ __forceinline__ void cp_wait1() {
    asm volatile("cp.async.wait_group 1;" ::: "memory");
}
__device__ __forceinline__ void cp_wait0() {
    asm volatile("cp.async.wait_group 0;" ::: "memory");
}

#define TSTRIDE 20                     // floats per smem row (16 data + 4 pad)
#define TILE_F (128 * TSTRIDE)

// ================= GEMM 1: xK projection (fp32 in, cvt in-register) =================
// Emits ONLY tf32 hi/lo copies of C (raw xK reconstructed as hi+lo where needed).
__global__ void __launch_bounds__(256) gemm_mma(
    const float* __restrict__ Ag, const float* __restrict__ Bg,
    float* __restrict__ Ch, float* __restrict__ Cl,
    int N, int Kd)
{
    __shared__ __align__(16) float smA[2][TILE_F];
    __shared__ __align__(16) float smB[2][TILE_F];

    const float* A = Ag;
    const float* B = Bg;
    const int m0 = blockIdx.y * 128;
    const int n0 = blockIdx.x * 128;
    const int tid = threadIdx.x, wid = tid >> 5, lane = tid & 31;
    const int wm = (wid & 1) * 64;
    const int wn = (wid >> 1) * 32;

    float acc[4][4][4];
    #pragma unroll
    for (int i = 0; i < 4; i++)
        #pragma unroll
        for (int j = 0; j < 4; j++)
            #pragma unroll
            for (int k = 0; k < 4; k++) acc[i][j][k] = 0.f;

    const int p_row0 = tid >> 2, p_q0 = tid & 3;
    const int p_row1 = (tid + 256) >> 2;

    const uint32_t sa0 = smem_u32(smA[0]);
    const uint32_t sb0 = smem_u32(smB[0]);

    const int a_r = (lane & 7) + ((lane >> 3) & 1) * 8;
    const int a_c = (lane >> 4) * 4;
    const int b_r = (lane & 7);
    const int b_c = ((lane >> 3) & 1) * 4;
    const uint32_t aOff = (uint32_t)(((wm + a_r) * TSTRIDE + a_c) * 4);
    const uint32_t bOff = (uint32_t)(((wn + b_r) * TSTRIDE + b_c) * 4);

    const int nc = Kd >> 4;

    auto issue = [&](int c, int bu) {
        const int k0 = c * 16;
        {
            long am = (long)(m0 + p_row0);
            long ar = am + (am >> 9);          // skip query rows
            cp16(sa0 + (uint32_t)((bu * TILE_F + p_row0 * TSTRIDE + p_q0 * 4) * 4),
                 A + ar * (long)Kd + k0 + p_q0 * 4);
            cp16(sb0 + (uint32_t)((bu * TILE_F + p_row0 * TSTRIDE + p_q0 * 4) * 4),
                 B + (long)(n0 + p_row0) * Kd + k0 + p_q0 * 4);
        }
        {
            long am = (long)(m0 + p_row1);
            long ar = am + (am >> 9);
            cp16(sa0 + (uint32_t)((bu * TILE_F + p_row1 * TSTRIDE + p_q0 * 4) * 4),
                 A + ar * (long)Kd + k0 + p_q0 * 4);
            cp16(sb0 + (uint32_t)((bu * TILE_F + p_row1 * TSTRIDE + p_q0 * 4) * 4),
                 B + (long)(n0 + p_row1) * Kd + k0 + p_q0 * 4);
        }
        cp_commit();
    };

    issue(0, 0);
    for (int c = 0; c < nc; c++) {
        const int bu = c & 1;
        if (c + 1 < nc) { issue(c + 1, bu ^ 1); cp_wait1(); }
        else            { cp_wait0(); }
        __syncthreads();

        const uint32_t aB = sa0 + (uint32_t)(bu * TILE_F * 4) + aOff;
        const uint32_t bB = sb0 + (uint32_t)(bu * TILE_F * 4) + bOff;

        #pragma unroll
        for (int k8 = 0; k8 < 2; k8++) {
            uint32_t ar[4][4], br[4][2];
            #pragma unroll
            for (int mi = 0; mi < 4; mi++)
                ldmx4(ar[mi], aB + (uint32_t)((mi * 16 * TSTRIDE) * 4 + k8 * 32));
            #pragma unroll
            for (int ni = 0; ni < 4; ni++)
                ldmx2(br[ni], bB + (uint32_t)((ni * 8 * TSTRIDE) * 4 + k8 * 32));

            uint32_t ah[4][4], bh[4][2];
            #pragma unroll
            for (int mi = 0; mi < 4; mi++)
                #pragma unroll
                for (int j = 0; j < 4; j++) ah[mi][j] = tf32_hi(ar[mi][j]);
            #pragma unroll
            for (int ni = 0; ni < 4; ni++)
                #pragma unroll
                for (int j = 0; j < 2; j++) bh[ni][j] = tf32_hi(br[ni][j]);

            #pragma unroll
            for (int mi = 0; mi < 4; mi++)
                #pragma unroll
                for (int ni = 0; ni < 4; ni++) mma8(acc[mi][ni], ah[mi], bh[ni]);

            uint32_t bl[4][2];
            #pragma unroll
            for (int ni = 0; ni < 4; ni++)
                #pragma unroll
                for (int j = 0; j < 2; j++) bl[ni][j] = tf32_lo(br[ni][j], bh[ni][j]);
            #pragma unroll
            for (int mi = 0; mi < 4; mi++)
                #pragma unroll
                for (int ni = 0; ni < 4; ni++) mma8(acc[mi][ni], ah[mi], bl[ni]);

            uint32_t al[4][4];
            #pragma unroll
            for (int mi = 0; mi < 4; mi++)
                #pragma unroll
                for (int j = 0; j < 4; j++) al[mi][j] = tf32_lo(ar[mi][j], ah[mi][j]);
            #pragma unroll
            for (int mi = 0; mi < 4; mi++)
                #pragma unroll
                for (int ni = 0; ni < 4; ni++) mma8(acc[mi][ni], al[mi], bh[ni]);
        }
        __syncthreads();
    }

    const int er = lane >> 2, ec = (lane & 3) * 2;
    #pragma unroll
    for (int mi = 0; mi < 4; mi++) {
        long row = m0 + wm + mi * 16 + er;
        #pragma unroll
        for (int ni = 0; ni < 4; ni++) {
            long col = n0 + wn + ni * 8 + ec;
            #pragma unroll
            for (int half = 0; half < 2; half++) {
                long off = (row + half * 8) * (long)N + col;
                float v0 = acc[mi][ni][half * 2 + 0];
                float v1 = acc[mi][ni][half * 2 + 1];
                uint32_t h0 = tf32_hi(__float_as_uint(v0));
                uint32_t h1 = tf32_hi(__float_as_uint(v1));
                *reinterpret_cast<float2*>(Ch + off) =
                    make_float2(__uint_as_float(h0), __uint_as_float(h1));
                *reinterpret_cast<float2*>(Cl + off) =
                    make_float2(__uint_as_float(tf32_lo(__float_as_uint(v0), h0)),
                                __uint_as_float(tf32_lo(__float_as_uint(v1), h1)));
            }
        }
    }
}

// ================= Merged L0 + G GEMM =================
// 74 tiles per batch: idx<64 -> L0 tile (N=2048, B=W_hi0 raw, in-reg cvt);
// idx>=64 -> G lower-triangular tile (10 tiles, both operands pre-split).
// Dynamic smem: [Ahi x2][Alo x2][Bhi x2][Blo x2] = 8*TILE_F floats.
__global__ void __launch_bounds__(256, 2) gemm_lg(
    const float* __restrict__ xKh, const float* __restrict__ xKl,
    const float* __restrict__ Whi0,
    float* __restrict__ L0g, float* __restrict__ Gg)
{
    extern __shared__ float sm[];
    const int z = blockIdx.z;
    const int idx = blockIdx.x;

    const float* Ah = xKh + (long)z * PT * PK;
    const float* Al = xKl + (long)z * PT * PK;
    const float* Bh;
    const float* Bl = nullptr;
    float* C;
    int m0, n0, N;
    bool bs;
    if (idx < 64) {
        bs = false;
        n0 = (idx & 15) * 128;
        m0 = (idx >> 4) * 128;
        N = PH;
        Bh = Whi0 + (long)z * PH * PK;
        C = L0g + (size_t)z * PT * PH;
    } else {
        int g = idx - 64;
        int by = (g >= 6) ? 3 : (g >= 3) ? 2 : (g >= 1) ? 1 : 0;
        int bx = g - (by * (by + 1)) / 2;
        bs = true;
        m0 = by * 128;
        n0 = bx * 128;
        N = PT;
        Bh = xKh + (long)z * PT * PK;
        Bl = xKl + (long)z * PT * PK;
        C = Gg + (size_t)z * PT * PT;
    }
    const int Kd = PK;

    const int tid = threadIdx.x, wid = tid >> 5, lane = tid & 31;
    const int wm = (wid & 1) * 64;
    const int wn = (wid >> 1) * 32;

    const uint32_t sbase = smem_u32(sm);
    const uint32_t OAH = 0, OAL = 2 * TILE_F, OBH = 4 * TILE_F, OBL = 6 * TILE_F;

    float acc[4][4][4];
    #pragma unroll
    for (int i = 0; i < 4; i++)
        #pragma unroll
        for (int j = 0; j < 4; j++)
            #pragma unroll
            for (int k = 0; k < 4; k++) acc[i][j][k] = 0.f;

    const int p_row0 = tid >> 2, p_q0 = tid & 3;
    const int p_row1 = (tid + 256) >> 2;

    const int a_r = (lane & 7) + ((lane >> 3) & 1) * 8;
    const int a_c = (lane >> 4) * 4;
    const int b_r = (lane & 7);
    const int b_c = ((lane >> 3) & 1) * 4;
    const uint32_t aOff = (uint32_t)(((wm + a_r) * TSTRIDE + a_c) * 4);
    const uint32_t bOff = (uint32_t)(((wn + b_r) * TSTRIDE + b_c) * 4);

    const int nc = Kd >> 4;

    auto issue = [&](int c, int bu) {
        const int k0 = c * 16;
        #pragma unroll
        for (int h = 0; h < 2; h++) {
            const int pr = h ? p_row1 : p_row0;
            const uint32_t dof = (uint32_t)((bu * TILE_F + pr * TSTRIDE + p_q0 * 4) * 4);
            const long aoff = (long)(m0 + pr) * Kd + k0 + p_q0 * 4;
            const long boff = (long)(n0 + pr) * Kd + k0 + p_q0 * 4;
            cp16(sbase + OAH * 4 + dof, Ah + aoff);
            cp16(sbase + OAL * 4 + dof, Al + aoff);
            cp16(sbase + OBH * 4 + dof, Bh + boff);
            if (bs) cp16(sbase + OBL * 4 + dof, Bl + boff);
        }
        cp_commit();
    };

    issue(0, 0);
    for (int c = 0; c < nc; c++) {
        const int bu = c & 1;
        if (c + 1 < nc) { issue(c + 1, bu ^ 1); cp_wait1(); }
        else            { cp_wait0(); }
        __syncthreads();

        const uint32_t bufo = (uint32_t)(bu * TILE_F * 4);
        const uint32_t aH = sbase + OAH * 4 + bufo + aOff;
        const uint32_t aL = sbase + OAL * 4 + bufo + aOff;
        const uint32_t bH = sbase + OBH * 4 + bufo + bOff;
        const uint32_t bL = sbase + OBL * 4 + bufo + bOff;

        #pragma unroll
        for (int k8 = 0; k8 < 2; k8++) {
            uint32_t ah[4][4], al[4][4], bh[4][2], bl[4][2];
            #pragma unroll
            for (int mi = 0; mi < 4; mi++) {
                const uint32_t o = (uint32_t)((mi * 16 * TSTRIDE) * 4 + k8 * 32);
                ldmx4(ah[mi], aH + o);
                ldmx4(al[mi], aL + o);
            }
            if (bs) {
                #pragma unroll
                for (int ni = 0; ni < 4; ni++) {
                    const uint32_t o = (uint32_t)((ni * 8 * TSTRIDE) * 4 + k8 * 32);
                    ldmx2(bh[ni], bH + o);
                    ldmx2(bl[ni], bL + o);
                }
            } else {
                #pragma unroll
                for (int ni = 0; ni < 4; ni++) {
                    uint32_t br[2];
                    ldmx2(br, bH + (uint32_t)((ni * 8 * TSTRIDE) * 4 + k8 * 32));
                    bh[ni][0] = tf32_hi(br[0]);
                    bh[ni][1] = tf32_hi(br[1]);
                    bl[ni][0] = tf32_lo(br[0], bh[ni][0]);
                    bl[ni][1] = tf32_lo(br[1], bh[ni][1]);
                }
            }

            #pragma unroll
            for (int mi = 0; mi < 4; mi++)
                #pragma unroll
                for (int ni = 0; ni < 4; ni++) mma8(acc[mi][ni], ah[mi], bh[ni]);
            #pragma unroll
            for (int mi = 0; mi < 4; mi++)
                #pragma unroll
                for (int ni = 0; ni < 4; ni++) mma8(acc[mi][ni], ah[mi], bl[ni]);
            #pragma unroll
            for (int mi = 0; mi < 4; mi++)
                #pragma unroll
                for (int ni = 0; ni < 4; ni++) mma8(acc[mi][ni], al[mi], bh[ni]);
        }
        __syncthreads();
    }

    const int er = lane >> 2, ec = (lane & 3) * 2;
    #pragma unroll
    for (int mi = 0; mi < 4; mi++) {
        long row = m0 + wm + mi * 16 + er;
        #pragma unroll
        for (int ni = 0; ni < 4; ni++) {
            long col = n0 + wn + ni * 8 + ec;
            *reinterpret_cast<float2*>(C + row * (long)N + col) =
                make_float2(acc[mi][ni][0], acc[mi][ni][1]);
            *reinterpret_cast<float2*>(C + (row + 8) * (long)N + col) =
                make_float2(acc[mi][ni][2], acc[mi][ni][3]);
        }
    }
}

// ---------------- xQ = x[b, 512, :] @ W_Q^T ----------------
__global__ void xq_kernel(const float* __restrict__ x, const float* __restrict__ WQ,
                          float* __restrict__ out_xq)
{
    int b = blockIdx.x;
    int w = threadIdx.x >> 5, lane = threadIdx.x & 31;
    int n = blockIdx.y * 8 + w;
    const float* xr = x + ((long)b * 513 + 512) * PD;
    const float* wr = WQ + (long)n * PD;
    float s = 0.f;
    for (int k = lane * 4; k < PD; k += 128) {
        float4 a = *reinterpret_cast<const float4*>(xr + k);
        float4 c = *reinterpret_cast<const float4*>(wr + k);
        s += a.x * c.x + a.y * c.y + a.z * c.z + a.w * c.w;
    }
    #pragma unroll
    for (int o = 16; o; o >>= 1) s += __shfl_down_sync(0xffffffffu, s, o);
    if (!lane) {
        g_xQ[b * PK + n] = s;
        out_xq[b * PK + n] = s;
    }
}

// ---------------- merged dots: q0[b,h]=W_hi0[b,h]·xQ ; qk[b,t]=(xKh+xKl)[b,t]·xQ ----------------
__global__ void __launch_bounds__(256) dots_kernel(const float* __restrict__ Whi0)
{
    int b = blockIdx.x, y = blockIdx.y;
    int w = threadIdx.x >> 5, lane = threadIdx.x & 31;
    const float* q = g_xQ + b * PK;
    if (y < PH / 8) {
        int r = y * 8 + w;
        const float* row = Whi0 + ((long)b * PH + r) * PK;
        float s = 0.f;
        for (int k = lane * 4; k < PK; k += 128) {
            float4 a = *reinterpret_cast<const float4*>(row + k);
            float4 qq = *reinterpret_cast<const float4*>(q + k);
            s += a.x * qq.x + a.y * qq.y + a.z * qq.z + a.w * qq.w;
        }
        #pragma unroll
        for (int o = 16; o; o >>= 1) s += __shfl_down_sync(0xffffffffu, s, o);
        if (!lane) g_q0[b * PH + r] = s;
    } else {
        int r = (y - PH / 8) * 8 + w;
        const float* rh = g_xKh + ((size_t)b * PT + r) * PK;
        const float* rl = g_xKl + ((size_t)b * PT + r) * PK;
        float s = 0.f;
        for (int k = lane * 4; k < PK; k += 128) {
            float4 ah = *reinterpret_cast<const float4*>(rh + k);
            float4 al = *reinterpret_cast<const float4*>(rl + k);
            float4 qq = *reinterpret_cast<const float4*>(q + k);
            s += (ah.x + al.x) * qq.x + (ah.y + al.y) * qq.y
               + (ah.z + al.z) * qq.z + (ah.w + al.w) * qq.w;
        }
        #pragma unroll
        for (int o = 16; o; o >>= 1) s += __shfl_down_sync(0xffffffffu, s, o);
        if (!lane) g_qk[b * PT + r] = s;
    }
}

// ---------------- scan (cp.async depth-5 ring) + inline softmax/weight-split ----------------
__global__ void __launch_bounds__(256) scan_kernel()
{
    const int b = blockIdx.x, tid = threadIdx.x;
    __shared__ __align__(16) float L0s[5][PH];   // 40 KB ring
    __shared__ __align__(16) float Gs[5][PT];    // 10 KB ring
    __shared__ unsigned redm[2][8];
    __shared__ unsigned redh[2][8];
    __shared__ float redf[8];

    const float* L0b = g_L0 + (size_t)b * PT * PH;
    const float* Gb  = g_G  + (size_t)b * PT * PT;
    const uint32_t sL = smem_u32(L0s);
    const uint32_t sG = smem_u32(Gs);

    int last[8];
    #pragma unroll
    for (int i = 0; i < 8; i++) last[i] = -1;

    auto issue_row = [&](int r) {
        const int sl = r % 5;
        cp16(sL + (uint32_t)((sl * PH + tid * 4) * 4),         L0b + (size_t)r * PH + tid * 4);
        cp16(sL + (uint32_t)((sl * PH + (tid + 256) * 4) * 4), L0b + (size_t)r * PH + (tid + 256) * 4);
        if (tid < 128)
            cp16(sG + (uint32_t)((sl * PT + tid * 4) * 4),     Gb + (size_t)r * PT + tid * 4);
    };

    #pragma unroll
    for (int r = 0; r < 4; r++) { issue_row(r); cp_commit(); }
    cp_wait3();
    __syncthreads();

    const int lane = tid & 31, w = tid >> 5;
    int slot = 0;

    for (int t = 0; t < PT; t++) {
        const float* gr = Gs[slot];
        const float* lr = L0s[slot];

        unsigned bestm;
        int besth;
        {
            float v = last[0] < 0 ? lr[tid] : gr[last[0]];
            unsigned u = __float_as_uint(v);
            bestm = (u & 0x80000000u) ? ~u : (u | 0x80000000u);
            besth = tid;
        }
        #pragma unroll
        for (int i = 1; i < 8; i++) {
            float v = last[i] < 0 ? lr[i * 256 + tid] : gr[last[i]];
            unsigned u = __float_as_uint(v);
            u = (u & 0x80000000u) ? ~u : (u | 0x80000000u);
            if (u > bestm) { bestm = u; besth = i * 256 + tid; }
        }
        unsigned m1 = __reduce_max_sync(0xffffffffu, bestm);
        unsigned hc = (bestm == m1) ? (unsigned)besth : 0xffffffffu;
        unsigned mh = __reduce_min_sync(0xffffffffu, hc);
        if (lane == 0) { redm[t & 1][w] = m1; redh[t & 1][w] = mh; }

        // prefetch row t+4 into slot (t+4)%5 (disjoint from any slot being read)
        if (t + 4 < PT) issue_row(t + 4);
        cp_commit();
        cp_wait3();
        __syncthreads();

        unsigned bm = redm[t & 1][0], bh = redh[t & 1][0];
        #pragma unroll
        for (int j = 1; j < 8; j++) {
            unsigned m2 = redm[t & 1][j], h2 = redh[t & 1][j];
            if (m2 > bm || (m2 == bm && h2 < bh)) { bm = m2; bh = h2; }
        }
        if ((int)(bh & 255u) == tid) last[bh >> 8] = t;

        slot = (slot == 4) ? 0 : slot + 1;
    }

    // ---- inline softmax + weight split (uses last[] in registers) ----
    g_wv[b * PT + tid]       = 0.f;
    g_wv[b * PT + 256 + tid] = 0.f;

    float l[8];
    float mx = -3.4e38f;
    #pragma unroll
    for (int i = 0; i < 8; i++) {
        int h = i * 256 + tid;
        int t = last[i];
        l[i] = (t < 0) ? g_q0[b * PH + h] : g_qk[b * PT + t];
        mx = fmaxf(mx, l[i]);
    }
    #pragma unroll
    for (int o = 16; o; o >>= 1) mx = fmaxf(mx, __shfl_xor_sync(0xffffffffu, mx, o));
    if (!lane) redf[w] = mx;
    __syncthreads();
    mx = redf[0];
    #pragma unroll
    for (int j = 1; j < 8; j++) mx = fmaxf(mx, redf[j]);

    float s = 0.f;
    #pragma unroll
    for (int i = 0; i < 8; i++) { l[i] = expf(l[i] - mx); s += l[i]; }
    #pragma unroll
    for (int o = 16; o; o >>= 1) s += __shfl_xor_sync(0xffffffffu, s, o);
    __syncthreads();
    if (!lane) redf[w] = s;
    __syncthreads();
    s = 0.f;
    #pragma unroll
    for (int j = 0; j < 8; j++) s += redf[j];

    float inv = 1.f / s;
    #pragma unroll
    for (int i = 0; i < 8; i++) {
        int h = i * 256 + tid;
        float wgt = l[i] * inv;
        if (last[i] < 0) {
            g_wt[b * PH + h] = wgt;
        } else {
            g_wt[b * PH + h] = 0.f;
            g_wv[b * PT + last[i]] = wgt;   // injective: each t owned by at most one slot
        }
    }
}

// ---------------- tail1: ybar (128 blocks) || reinst partials (512 blocks) ----------------
__global__ void __launch_bounds__(256) tail1_kernel(
    const float* __restrict__ x, const float* __restrict__ W_reinst0)
{
    int i = blockIdx.x, tid = threadIdx.x;
    __shared__ float sb[512];
    if (i < 128) {
        int b = i >> 2, d0 = (i & 3) * 256;
        sb[tid]       = g_wv[b * PT + tid];
        sb[256 + tid] = g_wv[b * PT + 256 + tid];
        __syncthreads();
        float yb = 0.f;
        const float* xb = x + (size_t)b * 513 * PD + d0 + tid;
        #pragma unroll 8
        for (int t = 0; t < PT; t++) yb += sb[t] * xb[(size_t)t * PD];
        g_ybar[b * PD + d0 + tid] = yb;
    } else {
        int j = i - 128;
        int z = j >> 7, low = j & 127;
        int b = low >> 2, d0 = (low & 3) * 256;
        sb[tid]       = g_wt[b * PH + z * 512 + tid];
        sb[256 + tid] = g_wt[b * PH + z * 512 + 256 + tid];
        __syncthreads();
        float acc = 0.f;
        const float* Wb = W_reinst0 + (size_t)b * PH * PD + (size_t)(z * 512) * PD + d0 + tid;
        #pragma unroll 8
        for (int h = 0; h < 512; h++) acc += sb[h] * Wb[(size_t)h * PD];
        g_rpart[((size_t)z * PB + b) * PD + d0 + tid] = acc;
    }
}

// ---------------- tail2: reinst reduce (128 blocks) || mhn (256 blocks) ----------------
__global__ void __launch_bounds__(256) tail2_kernel(
    const float* __restrict__ W_oh0, const float* __restrict__ W_V,
    float* __restrict__ out_reinst)
{
    int i = blockIdx.x, tid = threadIdx.x;
    if (i < 128) {
        int b = i >> 2;
        int d = (i & 3) * 256 + tid;
        float s = g_ybar[b * PD + d];
        #pragma unroll
        for (int z = 0; z < 4; z++) s += g_rpart[((size_t)z * PB + b) * PD + d];
        out_reinst[b * PD + d] = s;
    } else {
        int k = i - 128;
        int b = k >> 3, v0 = (k & 7) * 32;
        int lane = tid & 31, w = tid >> 5;
        __shared__ float wt_s[PH];
        __shared__ float yb_s[PD];
        #pragma unroll
        for (int q = 0; q < 8; q++) wt_s[q * 256 + tid] = g_wt[b * PH + q * 256 + tid];
        #pragma unroll
        for (int q = 0; q < 4; q++) yb_s[q * 256 + tid] = g_ybar[b * PD + q * 256 + tid];
        __syncthreads();

        for (int pass = 0; pass < 4; pass++) {
            int v = v0 + pass * 8 + w;
            const float* row = W_oh0 + ((long)b * PV + v) * PH;
            float s = 0.f;
            #pragma unroll 4
            for (int h = lane * 4; h < PH; h += 128) {
                float4 a = *reinterpret_cast<const float4*>(row + h);
                s += a.x * wt_s[h] + a.y * wt_s[h + 1] + a.z * wt_s[h + 2] + a.w * wt_s[h + 3];
            }
            const float* wvr = W_V + (long)v * PD;
            #pragma unroll 4
            for (int d = lane * 4; d < PD; d += 128) {
                float4 a = *reinterpret_cast<const float4*>(wvr + d);
                s += a.x * yb_s[d] + a.y * yb_s[d + 1] + a.z * yb_s[d + 2] + a.w * yb_s[d + 3];
            }
            #pragma unroll
            for (int o = 16; o; o >>= 1) s += __shfl_down_sync(0xffffffffu, s, o);
            if (!lane) g_mhn[b * PV + v] = s;
        }
    }
}

// ---------------- out[b,o] = mhn[b,:]@W_proj[o,:]  (grid: B x 8) ----------------
__global__ void __launch_bounds__(256) proj_kernel(
    const float* __restrict__ W_proj, float* __restrict__ outp)
{
    int b = blockIdx.x, tid = threadIdx.x, lane = tid & 31, w = tid >> 5;
    int o0 = blockIdx.y * 32;
    __shared__ float mhn_s[PV];
    if (tid < PV) mhn_s[tid] = g_mhn[b * PV + tid];
    __syncthreads();

    for (int pass = 0; pass < 4; pass++) {
        int o = o0 + pass * 8 + w;
        const float* pr = W_proj + (long)o * PV;
        float s = 0.f;
        for (int vv = lane * 4; vv < PV; vv += 128) {
            float4 a = *reinterpret_cast<const float4*>(pr + vv);
            s += a.x * mhn_s[vv] + a.y * mhn_s[vv + 1] + a.z * mhn_s[vv + 2] + a.w * mhn_s[vv + 3];
        }
        #pragma unroll
        for (int oo = 16; oo; oo >>= 1) s += __shfl_down_sync(0xffffffffu, s, oo);
        if (!lane) outp[b * PO + o] = s;
    }
}

// ---------------- launch ----------------
extern "C" void kernel_launch(void* const* d_in, const int* in_sizes, int n_in,
                              void* d_out, int out_size)
{
    const float* x         = (const float*)d_in[0];
    const float* W_Q       = (const float*)d_in[1];
    const float* W_K       = (const float*)d_in[2];
    const float* W_V       = (const float*)d_in[3];
    const float* W_proj    = (const float*)d_in[4];
    const float* W_hi0     = (const float*)d_in[5];
    const float* W_oh0     = (const float*)d_in[6];
    const float* W_reinst0 = (const float*)d_in[7];
    float* out = (float*)d_out;

    float *pxKh, *pxKl, *pL0, *pG;
    cudaGetSymbolAddress((void**)&pxKh, g_xKh);
    cudaGetSymbolAddress((void**)&pxKl, g_xKl);
    cudaGetSymbolAddress((void**)&pL0,  g_L0);
    cudaGetSymbolAddress((void**)&pG,   g_G);

    const int SM_LG = 8 * TILE_F * 4;   // 81920
    cudaFuncSetAttribute((const void*)gemm_lg,
                         cudaFuncAttributeMaxDynamicSharedMemorySize, SM_LG);

    // output layout: [out 32x256 | reinst 32x1024 | xQ 32x256]
    float* out_main   = out;
    float* out_reinst = out + PB * PO;
    float* out_xq     = out + PB * PO + PB * PD;

    // 1) xK = ctx @ W_K^T, stored as tf32 hi/lo pair
    gemm_mma<<<dim3(2, 128, 1), 256>>>(x, W_K, pxKh, pxKl, PK, PD);

    // 2) xQ
    xq_kernel<<<dim3(PB, PK / 8), 256>>>(x, W_Q, out_xq);

    // 3) merged L0 (64 tiles) + lower-triangular G (10 tiles) per batch
    gemm_lg<<<dim3(74, 1, PB), 256, SM_LG>>>(pxKh, pxKl, W_hi0, pL0, pG);

    // 4) merged final-logit dots (q0 over H, qk over T)
    dots_kernel<<<dim3(PB, PH / 8 + PT / 8), 256>>>(W_hi0);

    // 5) sequential winner scan + inline softmax/weight split
    scan_kernel<<<PB, 256>>>();

    // 6) tails
    tail1_kernel<<<640, 256>>>(x, W_reinst0);
    tail2_kernel<<<384, 256>>>(W_oh0, W_V, out_reinst);
    proj_kernel<<<dim3(PB, 8), 256>>>(W_proj, out_main);
}